// round 10
// baseline (speedup 1.0000x reference)
#include <cuda_runtime.h>
#include <cuda_bf16.h>
#include <cstdint>
#include <math.h>

#define BB 4
#define T_TXT 2048
#define DIM 2048
#define T_IMG 8
#define N_LAT 64
#define DIM_VIS 1024
#define HEADS 16
#define DIM_HEAD 64
#define INNER 1024
#define J_TOT (T_IMG * N_LAT)   // 512
#define LN_EPS 1e-5f
#define MTOT (BB * T_TXT)       // 8192

// ---------------- scratch (static device globals; no allocation) ----------------
__device__ __nv_bfloat16 g_xnh[MTOT * DIM];
__device__ __nv_bfloat16 g_xnl[MTOT * DIM];
__device__ __nv_bfloat16 g_mh [BB * J_TOT * DIM_VIS];
__device__ __nv_bfloat16 g_ml [BB * J_TOT * DIM_VIS];
__device__ __nv_bfloat16 g_wqh[INNER * DIM];          // Wq^T  [1024, 2048]
__device__ __nv_bfloat16 g_wql[INNER * DIM];
__device__ __nv_bfloat16 g_wkvh[2 * INNER * DIM_VIS]; // Wkv^T [2048, 1024]
__device__ __nv_bfloat16 g_wkvl[2 * INNER * DIM_VIS];
__device__ __nv_bfloat16 g_woh[DIM * INNER];          // Wo^T  [2048, 1024]
__device__ __nv_bfloat16 g_wol[DIM * INNER];
__device__ float g_q [MTOT * INNER];
__device__ float g_kv[BB * J_TOT * 2 * INNER];
__device__ __nv_bfloat16 g_aoh[MTOT * INNER];
__device__ __nv_bfloat16 g_aol[MTOT * INNER];
__device__ int g_tt[MTOT];

// ================= helpers =================
__device__ __forceinline__ uint32_t smem_u32(const void* p) {
    uint32_t a;
    asm("{ .reg .u64 t; cvta.to.shared.u64 t, %1; cvt.u32.u64 %0, t; }" : "=r"(a) : "l"(p));
    return a;
}
__device__ __forceinline__ void cp16(uint32_t d, const void* g) {
    asm volatile("cp.async.cg.shared.global [%0], [%1], 16;" :: "r"(d), "l"(g) : "memory");
}
__device__ __forceinline__ void cp_commit() { asm volatile("cp.async.commit_group;" ::: "memory"); }
template <int N> __device__ __forceinline__ void cp_wait() {
    asm volatile("cp.async.wait_group %0;" :: "n"(N) : "memory");
}
__device__ __forceinline__ void ldsm4(uint32_t* r, uint32_t addr) {
    asm volatile("ldmatrix.sync.aligned.m8n8.x4.shared.b16 {%0,%1,%2,%3}, [%4];"
        : "=r"(r[0]), "=r"(r[1]), "=r"(r[2]), "=r"(r[3]) : "r"(addr));
}
__device__ __forceinline__ void mma16816(float* c, const uint32_t* a, const uint32_t* b) {
    asm volatile("mma.sync.aligned.m16n8k16.row.col.f32.bf16.bf16.f32 "
        "{%0,%1,%2,%3}, {%4,%5,%6,%7}, {%8,%9}, {%0,%1,%2,%3};"
        : "+f"(c[0]), "+f"(c[1]), "+f"(c[2]), "+f"(c[3])
        : "r"(a[0]), "r"(a[1]), "r"(a[2]), "r"(a[3]), "r"(b[0]), "r"(b[1]));
}
// packed fp32x2 FMA (sm_100-family base PTX feature)
__device__ __forceinline__ void ffma2(unsigned long long& c, unsigned long long a, unsigned long long b) {
    asm("fma.rn.f32x2 %0, %1, %2, %0;" : "+l"(c) : "l"(a), "l"(b));
}
__device__ __forceinline__ unsigned long long pack2(float lo, float hi) {
    unsigned long long r;
    asm("mov.b64 %0, {%1, %2};" : "=l"(r) : "f"(lo), "f"(hi));
    return r;
}
__device__ __forceinline__ void unpack2(unsigned long long v, float& lo, float& hi) {
    asm("mov.b64 {%0, %1}, %2;" : "=f"(lo), "=f"(hi) : "l"(v));
}
__device__ __forceinline__ void split1(float v, __nv_bfloat16& h, __nv_bfloat16& l) {
    h = __float2bfloat16(v);
    l = __float2bfloat16(v - __bfloat162float(h));
}

// ---------------- text_time = cumsum(media_locations as 4-byte nonzero) ------
__global__ void cumsum_kernel(const unsigned int* __restrict__ ml) {
    __shared__ int seg[32];
    int b = blockIdx.x, t = threadIdx.x;
    const unsigned int* row = ml + b * T_TXT;
    int base = t * 64, local = 0;
    int pref[64];
    #pragma unroll 8
    for (int i = 0; i < 64; i++) { local += (row[base + i] != 0u) ? 1 : 0; pref[i] = local; }
    seg[t] = local;
    __syncwarp();
    int off = 0;
    for (int k = 0; k < t; k++) off += seg[k];
    int* out = g_tt + b * T_TXT + base;
    #pragma unroll 8
    for (int i = 0; i < 64; i++) out[i] = off + pref[i];
}

// ---------------- LayerNorm -> bf16 hi/lo ----------------
__global__ __launch_bounds__(256) void ln_kernel(const float* __restrict__ x,
                                                 const float* __restrict__ w,
                                                 const float* __restrict__ bb) {
    __shared__ float red[16];
    int row = blockIdx.x;
    const float* xr = x + (size_t)row * DIM;
    int base = threadIdx.x * 8;
    float4 a = *(const float4*)(xr + base);
    float4 c = *(const float4*)(xr + base + 4);
    float s  = a.x + a.y + a.z + a.w + c.x + c.y + c.z + c.w;
    float ss = a.x*a.x + a.y*a.y + a.z*a.z + a.w*a.w + c.x*c.x + c.y*c.y + c.z*c.z + c.w*c.w;
    #pragma unroll
    for (int o = 16; o > 0; o >>= 1) { s += __shfl_xor_sync(~0u, s, o); ss += __shfl_xor_sync(~0u, ss, o); }
    int warp = threadIdx.x >> 5, lane = threadIdx.x & 31;
    if (lane == 0) { red[warp] = s; red[warp + 8] = ss; }
    __syncthreads();
    s = 0.f; ss = 0.f;
    #pragma unroll
    for (int i = 0; i < 8; i++) { s += red[i]; ss += red[i + 8]; }
    float mu = s * (1.f / DIM);
    float r  = rsqrtf(ss * (1.f / DIM) - mu * mu + LN_EPS);

    float4 w0 = *(const float4*)(w + base), w1 = *(const float4*)(w + base + 4);
    float4 b0 = *(const float4*)(bb + base), b1 = *(const float4*)(bb + base + 4);
    float y[8];
    y[0]=(a.x-mu)*r*w0.x+b0.x; y[1]=(a.y-mu)*r*w0.y+b0.y; y[2]=(a.z-mu)*r*w0.z+b0.z; y[3]=(a.w-mu)*r*w0.w+b0.w;
    y[4]=(c.x-mu)*r*w1.x+b1.x; y[5]=(c.y-mu)*r*w1.y+b1.y; y[6]=(c.z-mu)*r*w1.z+b1.z; y[7]=(c.w-mu)*r*w1.w+b1.w;

    __align__(16) __nv_bfloat16 h[8], l[8];
    #pragma unroll
    for (int i = 0; i < 8; i++) split1(y[i], h[i], l[i]);
    size_t o = (size_t)row * DIM + base;
    *(uint4*)(g_xnh + o) = *(uint4*)h;
    *(uint4*)(g_xnl + o) = *(uint4*)l;
}

// ---------------- media fp32 -> hi/lo ----------------
__global__ __launch_bounds__(256) void split_kernel(const float* __restrict__ src,
                                                    __nv_bfloat16* __restrict__ dh,
                                                    __nv_bfloat16* __restrict__ dl) {
    int i = (blockIdx.x * 256 + threadIdx.x) * 4;
    float4 v = *(const float4*)(src + i);
    __align__(8) __nv_bfloat16 h[4], l[4];
    split1(v.x, h[0], l[0]); split1(v.y, h[1], l[1]);
    split1(v.z, h[2], l[2]); split1(v.w, h[3], l[3]);
    *(uint2*)(dh + i) = *(uint2*)h;
    *(uint2*)(dl + i) = *(uint2*)l;
}

// ---------------- weight transpose + split: W[K,N] -> Wt[N,K] hi/lo ----------
__global__ __launch_bounds__(256) void tsplit_kernel(const float* __restrict__ W,
                                                     __nv_bfloat16* __restrict__ Th,
                                                     __nv_bfloat16* __restrict__ Tl,
                                                     int K, int N) {
    __shared__ float t[32][33];
    int k0 = blockIdx.y * 32, n0 = blockIdx.x * 32;
    int tx = threadIdx.x & 31, ty = threadIdx.x >> 5;
    #pragma unroll
    for (int j = 0; j < 32; j += 8)
        t[ty + j][tx] = W[(size_t)(k0 + ty + j) * N + n0 + tx];
    __syncthreads();
    #pragma unroll
    for (int j = 0; j < 32; j += 8) {
        float v = t[tx][ty + j];
        __nv_bfloat16 h, l; split1(v, h, l);
        size_t o = (size_t)(n0 + ty + j) * K + k0 + tx;
        Th[o] = h; Tl[o] = l;
    }
}

// ============== HMMA split-bf16 GEMM: C(MxN) = A(MxK) @ Bt(NxK)^T ============
// 128x128x32 tile, 256 threads, warp grid 4(m)x2(n), warp tile 32x64.
// 2-stage cp.async, 2 CTAs/SM, ldmatrix.x4 fragment loads (issue-slot relief).
#define SST 40                    // smem row stride in bf16 (80 bytes)
#define ARR_B (128 * SST * 2)     // 10240 bytes per array
#define STAGE_B (4 * ARR_B)       // 40960
#define HG_SMEM (2 * STAGE_B)     // 81920

__global__ __launch_bounds__(256, 2) void hgemm(const __nv_bfloat16* __restrict__ Ah_,
                                                const __nv_bfloat16* __restrict__ Al_,
                                                const __nv_bfloat16* __restrict__ Bh_,
                                                const __nv_bfloat16* __restrict__ Bl_,
                                                float* __restrict__ C,
                                                int M, int N, int K) {
    extern __shared__ __align__(16) char smem[];
    uint32_t sb = smem_u32(smem);
    int tid = threadIdx.x, lane = tid & 31, wid = tid >> 5;
    int wm = wid >> 1, wn = wid & 1;      // warp grid 4x2
    int bm = blockIdx.y, bn = blockIdx.x;

    const __nv_bfloat16* srcs[4] = {
        Ah_ + (size_t)bm * 128 * K, Al_ + (size_t)bm * 128 * K,
        Bh_ + (size_t)bn * 128 * K, Bl_ + (size_t)bn * 128 * K };

    int lr = lane & 15;            // ldmatrix row-in-16
    int lc = lane >> 4;            // ldmatrix k-half
    int r0 = lane >> 2;            // mma output row-in-8
    int c0 = (lane & 3) * 2;       // mma output col pair

    float acc[2][8][4];
    #pragma unroll
    for (int mt = 0; mt < 2; mt++)
        #pragma unroll
        for (int nt = 0; nt < 8; nt++)
            #pragma unroll
            for (int q = 0; q < 4; q++) acc[mt][nt][q] = 0.f;

    int nchunk = K >> 5;

    auto load_chunk = [&](int c, int s) {
        uint32_t sbase = sb + s * STAGE_B;
        #pragma unroll
        for (int arr = 0; arr < 4; arr++) {
            #pragma unroll
            for (int i = 0; i < 2; i++) {
                int o = tid + 256 * i;          // 0..511
                int row = o >> 2, seg = o & 3;
                const void* g = srcs[arr] + (size_t)row * K + c * 32 + seg * 8;
                cp16(sbase + arr * ARR_B + row * (SST * 2) + seg * 16, g);
            }
        }
    };

    load_chunk(0, 0);
    cp_commit();

    for (int c = 0; c < nchunk; c++) {
        if (c + 1 < nchunk) { load_chunk(c + 1, (c + 1) & 1); cp_commit(); cp_wait<1>(); }
        else cp_wait<0>();
        __syncthreads();

        uint32_t st = sb + (c & 1) * STAGE_B;
        uint32_t Ahb = st, Alb = st + ARR_B, Bhb = st + 2 * ARR_B, Blb = st + 3 * ARR_B;

        #pragma unroll
        for (int ks = 0; ks < 2; ks++) {
            int k0 = ks * 16;
            uint32_t ah[2][4], al[2][4];
            #pragma unroll
            for (int mt = 0; mt < 2; mt++) {
                uint32_t off = (uint32_t)((wm * 32 + mt * 16 + lr) * (SST * 2) + (k0 + lc * 8) * 2);
                ldsm4(ah[mt], Ahb + off);
                ldsm4(al[mt], Alb + off);
            }
            // per-16-row B group: load frags via ldmatrix, consume immediately
            #pragma unroll
            for (int ng = 0; ng < 4; ng++) {
                uint32_t off = (uint32_t)((wn * 64 + ng * 16 + lr) * (SST * 2) + (k0 + lc * 8) * 2);
                uint32_t rh[4], rl[4];
                ldsm4(rh, Bhb + off);
                ldsm4(rl, Blb + off);
                uint32_t b0h[2] = {rh[0], rh[2]}, b1h[2] = {rh[1], rh[3]};
                uint32_t b0l[2] = {rl[0], rl[2]}, b1l[2] = {rl[1], rl[3]};
                int nt0 = 2 * ng, nt1 = 2 * ng + 1;
                mma16816(acc[0][nt0], ah[0], b0h);
                mma16816(acc[1][nt0], ah[1], b0h);
                mma16816(acc[0][nt0], ah[0], b0l);
                mma16816(acc[1][nt0], ah[1], b0l);
                mma16816(acc[0][nt0], al[0], b0h);
                mma16816(acc[1][nt0], al[1], b0h);
                mma16816(acc[0][nt1], ah[0], b1h);
                mma16816(acc[1][nt1], ah[1], b1h);
                mma16816(acc[0][nt1], ah[0], b1l);
                mma16816(acc[1][nt1], ah[1], b1l);
                mma16816(acc[0][nt1], al[0], b1h);
                mma16816(acc[1][nt1], al[1], b1h);
            }
        }
        __syncthreads();
    }

    #pragma unroll
    for (int mt = 0; mt < 2; mt++) {
        int row = bm * 128 + wm * 32 + mt * 16 + r0;
        #pragma unroll
        for (int nt = 0; nt < 8; nt++) {
            int col = bn * 128 + wn * 64 + nt * 8 + c0;
            float* p = C + (size_t)row * N + col;
            *(float2*)p             = make_float2(acc[mt][nt][0], acc[mt][nt][1]);
            *(float2*)(p + 8 * N)   = make_float2(acc[mt][nt][2], acc[mt][nt][3]);
        }
    }
}

// ---------------- attention: packed f32x2, K transposed in smem -------------
__device__ __forceinline__ void attn_scalar(const float* __restrict__ qrow,
                                            const float* kb_, const float* vb_,
                                            int ld, __nv_bfloat16* __restrict__ oh,
                                            __nv_bfloat16* __restrict__ ol) {
    float sc[64];
    #pragma unroll
    for (int j = 0; j < 64; j++) sc[j] = 0.f;
    for (int d0 = 0; d0 < 64; d0 += 4) {
        float4 qv = *(const float4*)(qrow + d0);
        #pragma unroll
        for (int j = 0; j < 64; j++) {
            float4 kv = *(const float4*)(kb_ + j * ld + d0);
            sc[j] += qv.x * kv.x + qv.y * kv.y + qv.z * kv.z + qv.w * kv.w;
        }
    }
    float m = sc[0];
    #pragma unroll
    for (int j = 1; j < 64; j++) m = fmaxf(m, sc[j]);
    float sum = 0.f;
    #pragma unroll
    for (int j = 0; j < 64; j++) { float p = __expf((sc[j] - m) * 0.125f); sc[j] = p; sum += p; }
    float inv = 1.f / sum;
    #pragma unroll
    for (int j = 0; j < 64; j++) sc[j] *= inv;
    for (int d0 = 0; d0 < 64; d0 += 4) {
        float o[4] = {0.f, 0.f, 0.f, 0.f};
        #pragma unroll
        for (int j = 0; j < 64; j++) {
            float4 vv = *(const float4*)(vb_ + j * ld + d0);
            o[0] += sc[j] * vv.x; o[1] += sc[j] * vv.y;
            o[2] += sc[j] * vv.z; o[3] += sc[j] * vv.w;
        }
        __align__(8) __nv_bfloat16 h[4], l[4];
        #pragma unroll
        for (int j = 0; j < 4; j++) split1(o[j], h[j], l[j]);
        *(uint2*)(oh + d0) = *(uint2*)h;
        *(uint2*)(ol + d0) = *(uint2*)l;
    }
}

__global__ __launch_bounds__(256) void attn_kernel() {
    __shared__ float KsT[64][68];                 // [d][j], padded
    __shared__ __align__(16) float Vs[64][64];    // [j][d]
    int s = blockIdx.x, h = blockIdx.y, b = blockIdx.z;
    int tid = threadIdx.x;
    int i = s * 256 + tid;

    int tt0 = g_tt[b * T_TXT + s * 256];
    int kb0 = tt0 - 1;
    if (kb0 < 0) kb0 = 0;
    if (kb0 > T_IMG - 1) kb0 = T_IMG - 1;

    const float* kvsrc = g_kv + ((size_t)(b * J_TOT + kb0 * 64)) * (2 * INNER) + h * DIM_HEAD;
    for (int idx = tid; idx < 1024; idx += 256) {
        int j = idx >> 4, d0 = (idx & 15) * 4;
        float4 kk = *(const float4*)(kvsrc + (size_t)j * (2 * INNER) + d0);
        KsT[d0][j] = kk.x; KsT[d0 + 1][j] = kk.y; KsT[d0 + 2][j] = kk.z; KsT[d0 + 3][j] = kk.w;
        *(float4*)(&Vs[j][d0]) = *(const float4*)(kvsrc + (size_t)j * (2 * INNER) + INNER + d0);
    }
    __syncthreads();

    int t = g_tt[b * T_TXT + i];
    size_t obase = (size_t)(b * T_TXT + i) * INNER + h * DIM_HEAD;
    __nv_bfloat16* oh = g_aoh + obase;
    __nv_bfloat16* ol = g_aol + obase;
    if (t == 0) {
        #pragma unroll
        for (int d0 = 0; d0 < 64; d0 += 4) {
            *(uint2*)(oh + d0) = make_uint2(0u, 0u);
            *(uint2*)(ol + d0) = make_uint2(0u, 0u);
        }
        return;
    }
    int kb = t - 1;
    const float* qrow = g_q + (size_t)(b * T_TXT + i) * INNER + h * DIM_HEAD;
    if (kb != kb0) {   // correctness fallback (not taken for the given inputs)
        const float* kg = g_kv + ((size_t)(b * J_TOT + kb * 64)) * (2 * INNER) + h * DIM_HEAD;
        attn_scalar(qrow, kg, kg + INNER, 2 * INNER, oh, ol);
        return;
    }

    // ---- QK^T: packed over j-pairs ----
    unsigned long long sc2[32];
    #pragma unroll
    for (int j = 0; j < 32; j++) sc2[j] = 0ull;
    for (int d0 = 0; d0 < 64; d0 += 4) {
        float4 q4 = *(const float4*)(qrow + d0);
        float qa[4] = {q4.x, q4.y, q4.z, q4.w};
        #pragma unroll
        for (int dd = 0; dd < 4; dd++) {
            unsigned long long qq = pack2(qa[dd], qa[dd]);
            const float* krow = &KsT[d0 + dd][0];
            #pragma unroll
            for (int j4 = 0; j4 < 16; j4++) {
                ulonglong2 kk = *(const ulonglong2*)(krow + j4 * 4);
                ffma2(sc2[2 * j4],     qq, kk.x);
                ffma2(sc2[2 * j4 + 1], qq, kk.y);
            }
        }
    }

    // ---- softmax ----
    float sc[64];
    #pragma unroll
    for (int j = 0; j < 32; j++) unpack2(sc2[j], sc[2 * j], sc[2 * j + 1]);
    float m = sc[0];
    #pragma unroll
    for (int j = 1; j < 64; j++) m = fmaxf(m, sc[j]);
    float sum = 0.f;
    #pragma unroll
    for (int j = 0; j < 64; j++) { float p = __expf((sc[j] - m) * 0.125f); sc[j] = p; sum += p; }
    float inv = 1.f / sum;
    #pragma unroll
    for (int j = 0; j < 64; j++) sc[j] *= inv;

    // ---- P @ V: packed over d-pairs ----
    unsigned long long o2[32];
    #pragma unroll
    for (int d = 0; d < 32; d++) o2[d] = 0ull;
    for (int j = 0; j < 64; j++) {
        unsigned long long pp = pack2(sc[j], sc[j]);
        const float* vrow = &Vs[j][0];
        #pragma unroll
        for (int d4 = 0; d4 < 16; d4++) {
            ulonglong2 vv = *(const ulonglong2*)(vrow + d4 * 4);
            ffma2(o2[2 * d4],     pp, vv.x);
            ffma2(o2[2 * d4 + 1], pp, vv.y);
        }
    }

    #pragma unroll
    for (int d4 = 0; d4 < 16; d4++) {
        float o[4];
        unpack2(o2[2 * d4], o[0], o[1]);
        unpack2(o2[2 * d4 + 1], o[2], o[3]);
        __align__(8) __nv_bfloat16 hh[4], ll[4];
        #pragma unroll
        for (int q = 0; q < 4; q++) split1(o[q], hh[q], ll[q]);
        *(uint2*)(oh + d4 * 4) = *(uint2*)hh;
        *(uint2*)(ol + d4 * 4) = *(uint2*)ll;
    }
}

// ---------------- launch ----------------
extern "C" void kernel_launch(void* const* d_in, const int* in_sizes, int n_in,
                              void* d_out, int out_size) {
    const float* x     = (const float*)d_in[0];
    const float* media = (const float*)d_in[1];
    const float* nw    = (const float*)d_in[2];
    const float* nb    = (const float*)d_in[3];
    const float* Wq    = (const float*)d_in[4];
    const float* Wkv   = (const float*)d_in[5];
    const float* Wo    = (const float*)d_in[6];
    const unsigned int* ml = (const unsigned int*)d_in[7];
    float* out = (float*)d_out;

    cudaFuncSetAttribute(hgemm, cudaFuncAttributeMaxDynamicSharedMemorySize, HG_SMEM);

    void *p_xnh, *p_xnl, *p_mh, *p_ml, *p_wqh, *p_wql, *p_wkvh, *p_wkvl, *p_woh, *p_wol,
         *p_q, *p_kv, *p_aoh, *p_aol;
    cudaGetSymbolAddress(&p_xnh, g_xnh);  cudaGetSymbolAddress(&p_xnl, g_xnl);
    cudaGetSymbolAddress(&p_mh, g_mh);    cudaGetSymbolAddress(&p_ml, g_ml);
    cudaGetSymbolAddress(&p_wqh, g_wqh);  cudaGetSymbolAddress(&p_wql, g_wql);
    cudaGetSymbolAddress(&p_wkvh, g_wkvh);cudaGetSymbolAddress(&p_wkvl, g_wkvl);
    cudaGetSymbolAddress(&p_woh, g_woh);  cudaGetSymbolAddress(&p_wol, g_wol);
    cudaGetSymbolAddress(&p_q, g_q);      cudaGetSymbolAddress(&p_kv, g_kv);
    cudaGetSymbolAddress(&p_aoh, g_aoh);  cudaGetSymbolAddress(&p_aol, g_aol);

    cumsum_kernel<<<BB, 32>>>(ml);
    ln_kernel<<<MTOT, 256>>>(x, nw, nb);
    split_kernel<<<(BB * J_TOT * DIM_VIS) / 1024, 256>>>(media, (__nv_bfloat16*)p_mh, (__nv_bfloat16*)p_ml);
    tsplit_kernel<<<dim3(INNER / 32, DIM / 32), 256>>>(Wq, (__nv_bfloat16*)p_wqh, (__nv_bfloat16*)p_wql, DIM, INNER);
    tsplit_kernel<<<dim3(2 * INNER / 32, DIM_VIS / 32), 256>>>(Wkv, (__nv_bfloat16*)p_wkvh, (__nv_bfloat16*)p_wkvl, DIM_VIS, 2 * INNER);
    tsplit_kernel<<<dim3(DIM / 32, INNER / 32), 256>>>(Wo, (__nv_bfloat16*)p_woh, (__nv_bfloat16*)p_wol, INNER, DIM);

    // Q = xn @ Wq : M=8192, N=1024, K=2048
    hgemm<<<dim3(INNER / 128, MTOT / 128), 256, HG_SMEM>>>(
        (const __nv_bfloat16*)p_xnh, (const __nv_bfloat16*)p_xnl,
        (const __nv_bfloat16*)p_wqh, (const __nv_bfloat16*)p_wql,
        (float*)p_q, MTOT, INNER, DIM);

    // KV = media @ Wkv : M=2048, N=2048, K=1024
    hgemm<<<dim3(2 * INNER / 128, (BB * J_TOT) / 128), 256, HG_SMEM>>>(
        (const __nv_bfloat16*)p_mh, (const __nv_bfloat16*)p_ml,
        (const __nv_bfloat16*)p_wkvh, (const __nv_bfloat16*)p_wkvl,
        (float*)p_kv, BB * J_TOT, 2 * INNER, DIM_VIS);

    attn_kernel<<<dim3(T_TXT / 256, HEADS, BB), 256>>>();

    // out = ao @ Wo : M=8192, N=2048, K=1024
    hgemm<<<dim3(DIM / 128, MTOT / 128), 256, HG_SMEM>>>(
        (const __nv_bfloat16*)p_aoh, (const __nv_bfloat16*)p_aol,
        (const __nv_bfloat16*)p_woh, (const __nv_bfloat16*)p_wol,
        out, MTOT, DIM, INNER);
}

// round 11
// speedup vs baseline: 1.0471x; 1.0471x over previous
#include <cuda_runtime.h>
#include <cuda_bf16.h>
#include <cstdint>
#include <math.h>

#define BB 4
#define T_TXT 2048
#define DIM 2048
#define T_IMG 8
#define N_LAT 64
#define DIM_VIS 1024
#define HEADS 16
#define DIM_HEAD 64
#define INNER 1024
#define J_TOT (T_IMG * N_LAT)   // 512
#define LN_EPS 1e-5f
#define MTOT (BB * T_TXT)       // 8192

// ---------------- scratch (static device globals; no allocation) ----------------
__device__ __nv_bfloat16 g_xnh[MTOT * DIM];
__device__ __nv_bfloat16 g_xnl[MTOT * DIM];
__device__ __nv_bfloat16 g_mh [BB * J_TOT * DIM_VIS];
__device__ __nv_bfloat16 g_ml [BB * J_TOT * DIM_VIS];
__device__ __nv_bfloat16 g_wqh[INNER * DIM];          // Wq^T  [1024, 2048]
__device__ __nv_bfloat16 g_wql[INNER * DIM];
__device__ __nv_bfloat16 g_wkvh[2 * INNER * DIM_VIS]; // Wkv^T [2048, 1024]
__device__ __nv_bfloat16 g_wkvl[2 * INNER * DIM_VIS];
__device__ __nv_bfloat16 g_woh[DIM * INNER];          // Wo^T  [2048, 1024]
__device__ __nv_bfloat16 g_wol[DIM * INNER];
__device__ float g_q [MTOT * INNER];
__device__ float g_kv[BB * J_TOT * 2 * INNER];
__device__ __nv_bfloat16 g_aoh[MTOT * INNER];
__device__ __nv_bfloat16 g_aol[MTOT * INNER];
__device__ int g_tt[MTOT];

// ================= helpers =================
__device__ __forceinline__ uint32_t smem_u32(const void* p) {
    uint32_t a;
    asm("{ .reg .u64 t; cvta.to.shared.u64 t, %1; cvt.u32.u64 %0, t; }" : "=r"(a) : "l"(p));
    return a;
}
__device__ __forceinline__ uint32_t lds32(uint32_t a) {
    uint32_t v;
    asm volatile("ld.shared.b32 %0, [%1];" : "=r"(v) : "r"(a));
    return v;
}
__device__ __forceinline__ void cp16(uint32_t d, const void* g) {
    asm volatile("cp.async.cg.shared.global [%0], [%1], 16;" :: "r"(d), "l"(g) : "memory");
}
__device__ __forceinline__ void cp_commit() { asm volatile("cp.async.commit_group;" ::: "memory"); }
template <int N> __device__ __forceinline__ void cp_wait() {
    asm volatile("cp.async.wait_group %0;" :: "n"(N) : "memory");
}
__device__ __forceinline__ void mma16816(float* c, const uint32_t* a, const uint32_t* b) {
    asm volatile("mma.sync.aligned.m16n8k16.row.col.f32.bf16.bf16.f32 "
        "{%0,%1,%2,%3}, {%4,%5,%6,%7}, {%8,%9}, {%0,%1,%2,%3};"
        : "+f"(c[0]), "+f"(c[1]), "+f"(c[2]), "+f"(c[3])
        : "r"(a[0]), "r"(a[1]), "r"(a[2]), "r"(a[3]), "r"(b[0]), "r"(b[1]));
}
// packed fp32x2 FMA (sm_100-family base PTX feature)
__device__ __forceinline__ void ffma2(unsigned long long& c, unsigned long long a, unsigned long long b) {
    asm("fma.rn.f32x2 %0, %1, %2, %0;" : "+l"(c) : "l"(a), "l"(b));
}
__device__ __forceinline__ unsigned long long pack2(float lo, float hi) {
    unsigned long long r;
    asm("mov.b64 %0, {%1, %2};" : "=l"(r) : "f"(lo), "f"(hi));
    return r;
}
__device__ __forceinline__ void unpack2(unsigned long long v, float& lo, float& hi) {
    asm("mov.b64 {%0, %1}, %2;" : "=f"(lo), "=f"(hi) : "l"(v));
}
__device__ __forceinline__ void split1(float v, __nv_bfloat16& h, __nv_bfloat16& l) {
    h = __float2bfloat16(v);
    l = __float2bfloat16(v - __bfloat162float(h));
}

// ---------------- text_time = cumsum(media_locations as 4-byte nonzero) ------
__global__ void cumsum_kernel(const unsigned int* __restrict__ ml) {
    __shared__ int seg[32];
    int b = blockIdx.x, t = threadIdx.x;
    const unsigned int* row = ml + b * T_TXT;
    int base = t * 64, local = 0;
    int pref[64];
    #pragma unroll 8
    for (int i = 0; i < 64; i++) { local += (row[base + i] != 0u) ? 1 : 0; pref[i] = local; }
    seg[t] = local;
    __syncwarp();
    int off = 0;
    for (int k = 0; k < t; k++) off += seg[k];
    int* out = g_tt + b * T_TXT + base;
    #pragma unroll 8
    for (int i = 0; i < 64; i++) out[i] = off + pref[i];
}

// ---------------- LayerNorm -> bf16 hi/lo ----------------
__global__ __launch_bounds__(256) void ln_kernel(const float* __restrict__ x,
                                                 const float* __restrict__ w,
                                                 const float* __restrict__ bb) {
    __shared__ float red[16];
    int row = blockIdx.x;
    const float* xr = x + (size_t)row * DIM;
    int base = threadIdx.x * 8;
    float4 a = *(const float4*)(xr + base);
    float4 c = *(const float4*)(xr + base + 4);
    float s  = a.x + a.y + a.z + a.w + c.x + c.y + c.z + c.w;
    float ss = a.x*a.x + a.y*a.y + a.z*a.z + a.w*a.w + c.x*c.x + c.y*c.y + c.z*c.z + c.w*c.w;
    #pragma unroll
    for (int o = 16; o > 0; o >>= 1) { s += __shfl_xor_sync(~0u, s, o); ss += __shfl_xor_sync(~0u, ss, o); }
    int warp = threadIdx.x >> 5, lane = threadIdx.x & 31;
    if (lane == 0) { red[warp] = s; red[warp + 8] = ss; }
    __syncthreads();
    s = 0.f; ss = 0.f;
    #pragma unroll
    for (int i = 0; i < 8; i++) { s += red[i]; ss += red[i + 8]; }
    float mu = s * (1.f / DIM);
    float r  = rsqrtf(ss * (1.f / DIM) - mu * mu + LN_EPS);

    float4 w0 = *(const float4*)(w + base), w1 = *(const float4*)(w + base + 4);
    float4 b0 = *(const float4*)(bb + base), b1 = *(const float4*)(bb + base + 4);
    float y[8];
    y[0]=(a.x-mu)*r*w0.x+b0.x; y[1]=(a.y-mu)*r*w0.y+b0.y; y[2]=(a.z-mu)*r*w0.z+b0.z; y[3]=(a.w-mu)*r*w0.w+b0.w;
    y[4]=(c.x-mu)*r*w1.x+b1.x; y[5]=(c.y-mu)*r*w1.y+b1.y; y[6]=(c.z-mu)*r*w1.z+b1.z; y[7]=(c.w-mu)*r*w1.w+b1.w;

    __align__(16) __nv_bfloat16 h[8], l[8];
    #pragma unroll
    for (int i = 0; i < 8; i++) split1(y[i], h[i], l[i]);
    size_t o = (size_t)row * DIM + base;
    *(uint4*)(g_xnh + o) = *(uint4*)h;
    *(uint4*)(g_xnl + o) = *(uint4*)l;
}

// ---------------- media fp32 -> hi/lo ----------------
__global__ __launch_bounds__(256) void split_kernel(const float* __restrict__ src,
                                                    __nv_bfloat16* __restrict__ dh,
                                                    __nv_bfloat16* __restrict__ dl) {
    int i = (blockIdx.x * 256 + threadIdx.x) * 4;
    float4 v = *(const float4*)(src + i);
    __align__(8) __nv_bfloat16 h[4], l[4];
    split1(v.x, h[0], l[0]); split1(v.y, h[1], l[1]);
    split1(v.z, h[2], l[2]); split1(v.w, h[3], l[3]);
    *(uint2*)(dh + i) = *(uint2*)h;
    *(uint2*)(dl + i) = *(uint2*)l;
}

// ---------------- weight transpose + split: W[K,N] -> Wt[N,K] hi/lo ----------
__global__ __launch_bounds__(256) void tsplit_kernel(const float* __restrict__ W,
                                                     __nv_bfloat16* __restrict__ Th,
                                                     __nv_bfloat16* __restrict__ Tl,
                                                     int K, int N) {
    __shared__ float t[32][33];
    int k0 = blockIdx.y * 32, n0 = blockIdx.x * 32;
    int tx = threadIdx.x & 31, ty = threadIdx.x >> 5;
    #pragma unroll
    for (int j = 0; j < 32; j += 8)
        t[ty + j][tx] = W[(size_t)(k0 + ty + j) * N + n0 + tx];
    __syncthreads();
    #pragma unroll
    for (int j = 0; j < 32; j += 8) {
        float v = t[tx][ty + j];
        __nv_bfloat16 h, l; split1(v, h, l);
        size_t o = (size_t)(n0 + ty + j) * K + k0 + tx;
        Th[o] = h; Tl[o] = l;
    }
}

// ============== HMMA split-bf16 GEMM: C(MxN) = A(MxK) @ Bt(NxK)^T ============
// 128x128x32 tile, 256 threads, warp grid 4(m)x2(n), warp tile 32x64.
// 2-stage cp.async, 2 CTAs/SM, ONE __syncthreads per chunk:
// at top of iter c, cp_wait<0> + sync guarantees (a) chunk c visible and
// (b) all warps done reading stage (c+1)&1 (= compute stage of iter c-1),
// which is exactly the stage the subsequent load of chunk c+1 overwrites.
#define SST 40                    // smem row stride in bf16 (80 bytes)
#define ARR_B (128 * SST * 2)     // 10240 bytes per array
#define STAGE_B (4 * ARR_B)       // 40960
#define HG_SMEM (2 * STAGE_B)     // 81920

__global__ __launch_bounds__(256, 2) void hgemm(const __nv_bfloat16* __restrict__ Ah_,
                                                const __nv_bfloat16* __restrict__ Al_,
                                                const __nv_bfloat16* __restrict__ Bh_,
                                                const __nv_bfloat16* __restrict__ Bl_,
                                                float* __restrict__ C,
                                                int M, int N, int K) {
    extern __shared__ __align__(16) char smem[];
    uint32_t sb = smem_u32(smem);
    int tid = threadIdx.x, lane = tid & 31, wid = tid >> 5;
    int wm = wid >> 1, wn = wid & 1;      // warp grid 4x2
    int bm = blockIdx.y, bn = blockIdx.x;

    const __nv_bfloat16* srcs[4] = {
        Ah_ + (size_t)bm * 128 * K, Al_ + (size_t)bm * 128 * K,
        Bh_ + (size_t)bn * 128 * K, Bl_ + (size_t)bn * 128 * K };

    int r0 = lane >> 2;            // 0..7
    int c0 = (lane & 3) * 2;       // 0,2,4,6

    float acc[2][8][4];
    #pragma unroll
    for (int mt = 0; mt < 2; mt++)
        #pragma unroll
        for (int nt = 0; nt < 8; nt++)
            #pragma unroll
            for (int q = 0; q < 4; q++) acc[mt][nt][q] = 0.f;

    int nchunk = K >> 5;

    auto load_chunk = [&](int c, int s) {
        uint32_t sbase = sb + s * STAGE_B;
        #pragma unroll
        for (int arr = 0; arr < 4; arr++) {
            #pragma unroll
            for (int i = 0; i < 2; i++) {
                int o = tid + 256 * i;          // 0..511
                int row = o >> 2, seg = o & 3;
                const void* g = srcs[arr] + (size_t)row * K + c * 32 + seg * 8;
                cp16(sbase + arr * ARR_B + row * (SST * 2) + seg * 16, g);
            }
        }
    };

    load_chunk(0, 0);
    cp_commit();

    for (int c = 0; c < nchunk; c++) {
        cp_wait<0>();        // chunk c resident
        __syncthreads();     // + all warps done with iter c-1's stage -> safe to overwrite

        if (c + 1 < nchunk) { load_chunk(c + 1, (c + 1) & 1); cp_commit(); }

        uint32_t st = sb + (c & 1) * STAGE_B;
        uint32_t Ahb = st, Alb = st + ARR_B, Bhb = st + 2 * ARR_B, Blb = st + 3 * ARR_B;

        #pragma unroll
        for (int ks = 0; ks < 2; ks++) {
            int k0 = ks * 16;
            uint32_t ah[2][4], al[2][4];
            #pragma unroll
            for (int mt = 0; mt < 2; mt++) {
                uint32_t ro = (uint32_t)((wm * 32 + mt * 16 + r0) * (SST * 2) + (k0 + c0) * 2);
                ah[mt][0] = lds32(Ahb + ro);
                ah[mt][1] = lds32(Ahb + ro + 8 * (SST * 2));
                ah[mt][2] = lds32(Ahb + ro + 16);
                ah[mt][3] = lds32(Ahb + ro + 8 * (SST * 2) + 16);
                al[mt][0] = lds32(Alb + ro);
                al[mt][1] = lds32(Alb + ro + 8 * (SST * 2));
                al[mt][2] = lds32(Alb + ro + 16);
                al[mt][3] = lds32(Alb + ro + 8 * (SST * 2) + 16);
            }
            // per-nt: load B fragments and consume immediately (low live-reg count)
            #pragma unroll
            for (int nt = 0; nt < 8; nt++) {
                uint32_t no = (uint32_t)((wn * 64 + nt * 8 + r0) * (SST * 2) + (k0 + c0) * 2);
                uint32_t bh[2], bl[2];
                bh[0] = lds32(Bhb + no);
                bh[1] = lds32(Bhb + no + 16);
                bl[0] = lds32(Blb + no);
                bl[1] = lds32(Blb + no + 16);
                mma16816(acc[0][nt], ah[0], bh);
                mma16816(acc[1][nt], ah[1], bh);
                mma16816(acc[0][nt], ah[0], bl);
                mma16816(acc[1][nt], ah[1], bl);
                mma16816(acc[0][nt], al[0], bh);
                mma16816(acc[1][nt], al[1], bh);
            }
        }
    }

    #pragma unroll
    for (int mt = 0; mt < 2; mt++) {
        int row = bm * 128 + wm * 32 + mt * 16 + r0;
        #pragma unroll
        for (int nt = 0; nt < 8; nt++) {
            int col = bn * 128 + wn * 64 + nt * 8 + c0;
            float* p = C + (size_t)row * N + col;
            *(float2*)p             = make_float2(acc[mt][nt][0], acc[mt][nt][1]);
            *(float2*)(p + 8 * N)   = make_float2(acc[mt][nt][2], acc[mt][nt][3]);
        }
    }
}

// ---------------- attention: packed f32x2, K transposed in smem -------------
__device__ __forceinline__ void attn_scalar(const float* __restrict__ qrow,
                                            const float* kb_, const float* vb_,
                                            int ld, __nv_bfloat16* __restrict__ oh,
                                            __nv_bfloat16* __restrict__ ol) {
    float sc[64];
    #pragma unroll
    for (int j = 0; j < 64; j++) sc[j] = 0.f;
    for (int d0 = 0; d0 < 64; d0 += 4) {
        float4 qv = *(const float4*)(qrow + d0);
        #pragma unroll
        for (int j = 0; j < 64; j++) {
            float4 kv = *(const float4*)(kb_ + j * ld + d0);
            sc[j] += qv.x * kv.x + qv.y * kv.y + qv.z * kv.z + qv.w * kv.w;
        }
    }
    float m = sc[0];
    #pragma unroll
    for (int j = 1; j < 64; j++) m = fmaxf(m, sc[j]);
    float sum = 0.f;
    #pragma unroll
    for (int j = 0; j < 64; j++) { float p = __expf((sc[j] - m) * 0.125f); sc[j] = p; sum += p; }
    float inv = 1.f / sum;
    #pragma unroll
    for (int j = 0; j < 64; j++) sc[j] *= inv;
    for (int d0 = 0; d0 < 64; d0 += 4) {
        float o[4] = {0.f, 0.f, 0.f, 0.f};
        #pragma unroll
        for (int j = 0; j < 64; j++) {
            float4 vv = *(const float4*)(vb_ + j * ld + d0);
            o[0] += sc[j] * vv.x; o[1] += sc[j] * vv.y;
            o[2] += sc[j] * vv.z; o[3] += sc[j] * vv.w;
        }
        __align__(8) __nv_bfloat16 h[4], l[4];
        #pragma unroll
        for (int j = 0; j < 4; j++) split1(o[j], h[j], l[j]);
        *(uint2*)(oh + d0) = *(uint2*)h;
        *(uint2*)(ol + d0) = *(uint2*)l;
    }
}

__global__ __launch_bounds__(256) void attn_kernel() {
    __shared__ float KsT[64][68];                 // [d][j], padded
    __shared__ __align__(16) float Vs[64][64];    // [j][d]
    int s = blockIdx.x, h = blockIdx.y, b = blockIdx.z;
    int tid = threadIdx.x;
    int i = s * 256 + tid;

    int tt0 = g_tt[b * T_TXT + s * 256];
    int kb0 = tt0 - 1;
    if (kb0 < 0) kb0 = 0;
    if (kb0 > T_IMG - 1) kb0 = T_IMG - 1;

    const float* kvsrc = g_kv + ((size_t)(b * J_TOT + kb0 * 64)) * (2 * INNER) + h * DIM_HEAD;
    for (int idx = tid; idx < 1024; idx += 256) {
        int j = idx >> 4, d0 = (idx & 15) * 4;
        float4 kk = *(const float4*)(kvsrc + (size_t)j * (2 * INNER) + d0);
        KsT[d0][j] = kk.x; KsT[d0 + 1][j] = kk.y; KsT[d0 + 2][j] = kk.z; KsT[d0 + 3][j] = kk.w;
        *(float4*)(&Vs[j][d0]) = *(const float4*)(kvsrc + (size_t)j * (2 * INNER) + INNER + d0);
    }
    __syncthreads();

    int t = g_tt[b * T_TXT + i];
    size_t obase = (size_t)(b * T_TXT + i) * INNER + h * DIM_HEAD;
    __nv_bfloat16* oh = g_aoh + obase;
    __nv_bfloat16* ol = g_aol + obase;
    if (t == 0) {
        #pragma unroll
        for (int d0 = 0; d0 < 64; d0 += 4) {
            *(uint2*)(oh + d0) = make_uint2(0u, 0u);
            *(uint2*)(ol + d0) = make_uint2(0u, 0u);
        }
        return;
    }
    int kb = t - 1;
    const float* qrow = g_q + (size_t)(b * T_TXT + i) * INNER + h * DIM_HEAD;
    if (kb != kb0) {   // correctness fallback (not taken for the given inputs)
        const float* kg = g_kv + ((size_t)(b * J_TOT + kb * 64)) * (2 * INNER) + h * DIM_HEAD;
        attn_scalar(qrow, kg, kg + INNER, 2 * INNER, oh, ol);
        return;
    }

    // ---- QK^T: packed over j-pairs ----
    unsigned long long sc2[32];
    #pragma unroll
    for (int j = 0; j < 32; j++) sc2[j] = 0ull;
    for (int d0 = 0; d0 < 64; d0 += 4) {
        float4 q4 = *(const float4*)(qrow + d0);
        float qa[4] = {q4.x, q4.y, q4.z, q4.w};
        #pragma unroll
        for (int dd = 0; dd < 4; dd++) {
            unsigned long long qq = pack2(qa[dd], qa[dd]);
            const float* krow = &KsT[d0 + dd][0];
            #pragma unroll
            for (int j4 = 0; j4 < 16; j4++) {
                ulonglong2 kk = *(const ulonglong2*)(krow + j4 * 4);
                ffma2(sc2[2 * j4],     qq, kk.x);
                ffma2(sc2[2 * j4 + 1], qq, kk.y);
            }
        }
    }

    // ---- softmax ----
    float sc[64];
    #pragma unroll
    for (int j = 0; j < 32; j++) unpack2(sc2[j], sc[2 * j], sc[2 * j + 1]);
    float m = sc[0];
    #pragma unroll
    for (int j = 1; j < 64; j++) m = fmaxf(m, sc[j]);
    float sum = 0.f;
    #pragma unroll
    for (int j = 0; j < 64; j++) { float p = __expf((sc[j] - m) * 0.125f); sc[j] = p; sum += p; }
    float inv = 1.f / sum;
    #pragma unroll
    for (int j = 0; j < 64; j++) sc[j] *= inv;

    // ---- P @ V: packed over d-pairs ----
    unsigned long long o2[32];
    #pragma unroll
    for (int d = 0; d < 32; d++) o2[d] = 0ull;
    for (int j = 0; j < 64; j++) {
        unsigned long long pp = pack2(sc[j], sc[j]);
        const float* vrow = &Vs[j][0];
        #pragma unroll
        for (int d4 = 0; d4 < 16; d4++) {
            ulonglong2 vv = *(const ulonglong2*)(vrow + d4 * 4);
            ffma2(o2[2 * d4],     pp, vv.x);
            ffma2(o2[2 * d4 + 1], pp, vv.y);
        }
    }

    #pragma unroll
    for (int d4 = 0; d4 < 16; d4++) {
        float o[4];
        unpack2(o2[2 * d4], o[0], o[1]);
        unpack2(o2[2 * d4 + 1], o[2], o[3]);
        __align__(8) __nv_bfloat16 hh[4], ll[4];
        #pragma unroll
        for (int q = 0; q < 4; q++) split1(o[q], hh[q], ll[q]);
        *(uint2*)(oh + d4 * 4) = *(uint2*)hh;
        *(uint2*)(ol + d4 * 4) = *(uint2*)ll;
    }
}

// ---------------- launch ----------------
extern "C" void kernel_launch(void* const* d_in, const int* in_sizes, int n_in,
                              void* d_out, int out_size) {
    const float* x     = (const float*)d_in[0];
    const float* media = (const float*)d_in[1];
    const float* nw    = (const float*)d_in[2];
    const float* nb    = (const float*)d_in[3];
    const float* Wq    = (const float*)d_in[4];
    const float* Wkv   = (const float*)d_in[5];
    const float* Wo    = (const float*)d_in[6];
    const unsigned int* ml = (const unsigned int*)d_in[7];
    float* out = (float*)d_out;

    cudaFuncSetAttribute(hgemm, cudaFuncAttributeMaxDynamicSharedMemorySize, HG_SMEM);

    void *p_xnh, *p_xnl, *p_mh, *p_ml, *p_wqh, *p_wql, *p_wkvh, *p_wkvl, *p_woh, *p_wol,
         *p_q, *p_kv, *p_aoh, *p_aol;
    cudaGetSymbolAddress(&p_xnh, g_xnh);  cudaGetSymbolAddress(&p_xnl, g_xnl);
    cudaGetSymbolAddress(&p_mh, g_mh);    cudaGetSymbolAddress(&p_ml, g_ml);
    cudaGetSymbolAddress(&p_wqh, g_wqh);  cudaGetSymbolAddress(&p_wql, g_wql);
    cudaGetSymbolAddress(&p_wkvh, g_wkvh);cudaGetSymbolAddress(&p_wkvl, g_wkvl);
    cudaGetSymbolAddress(&p_woh, g_woh);  cudaGetSymbolAddress(&p_wol, g_wol);
    cudaGetSymbolAddress(&p_q, g_q);      cudaGetSymbolAddress(&p_kv, g_kv);
    cudaGetSymbolAddress(&p_aoh, g_aoh);  cudaGetSymbolAddress(&p_aol, g_aol);

    cumsum_kernel<<<BB, 32>>>(ml);
    ln_kernel<<<MTOT, 256>>>(x, nw, nb);
    split_kernel<<<(BB * J_TOT * DIM_VIS) / 1024, 256>>>(media, (__nv_bfloat16*)p_mh, (__nv_bfloat16*)p_ml);
    tsplit_kernel<<<dim3(INNER / 32, DIM / 32), 256>>>(Wq, (__nv_bfloat16*)p_wqh, (__nv_bfloat16*)p_wql, DIM, INNER);
    tsplit_kernel<<<dim3(2 * INNER / 32, DIM_VIS / 32), 256>>>(Wkv, (__nv_bfloat16*)p_wkvh, (__nv_bfloat16*)p_wkvl, DIM_VIS, 2 * INNER);
    tsplit_kernel<<<dim3(DIM / 32, INNER / 32), 256>>>(Wo, (__nv_bfloat16*)p_woh, (__nv_bfloat16*)p_wol, INNER, DIM);

    // Q = xn @ Wq : M=8192, N=1024, K=2048
    hgemm<<<dim3(INNER / 128, MTOT / 128), 256, HG_SMEM>>>(
        (const __nv_bfloat16*)p_xnh, (const __nv_bfloat16*)p_xnl,
        (const __nv_bfloat16*)p_wqh, (const __nv_bfloat16*)p_wql,
        (float*)p_q, MTOT, INNER, DIM);

    // KV = media @ Wkv : M=2048, N=2048, K=1024
    hgemm<<<dim3(2 * INNER / 128, (BB * J_TOT) / 128), 256, HG_SMEM>>>(
        (const __nv_bfloat16*)p_mh, (const __nv_bfloat16*)p_ml,
        (const __nv_bfloat16*)p_wkvh, (const __nv_bfloat16*)p_wkvl,
        (float*)p_kv, BB * J_TOT, 2 * INNER, DIM_VIS);

    attn_kernel<<<dim3(T_TXT / 256, HEADS, BB), 256>>>();

    // out = ao @ Wo : M=8192, N=2048, K=1024
    hgemm<<<dim3(DIM / 128, MTOT / 128), 256, HG_SMEM>>>(
        (const __nv_bfloat16*)p_aoh, (const __nv_bfloat16*)p_aol,
        (const __nv_bfloat16*)p_woh, (const __nv_bfloat16*)p_wol,
        out, MTOT, DIM, INNER);
}

// round 14
// speedup vs baseline: 1.0833x; 1.0346x over previous
#include <cuda_runtime.h>
#include <cuda_bf16.h>
#include <cstdint>
#include <math.h>

#define BB 4
#define T_TXT 2048
#define DIM 2048
#define T_IMG 8
#define N_LAT 64
#define DIM_VIS 1024
#define HEADS 16
#define DIM_HEAD 64
#define INNER 1024
#define J_TOT (T_IMG * N_LAT)   // 512
#define LN_EPS 1e-5f
#define MTOT (BB * T_TXT)       // 8192

// ---------------- scratch (static device globals; no allocation) ----------------
__device__ __nv_bfloat16 g_xnh[MTOT * DIM];
__device__ __nv_bfloat16 g_xnl[MTOT * DIM];
__device__ __nv_bfloat16 g_mh [BB * J_TOT * DIM_VIS];
__device__ __nv_bfloat16 g_ml [BB * J_TOT * DIM_VIS];
__device__ __nv_bfloat16 g_wqh[INNER * DIM];          // Wq^T  [1024, 2048]
__device__ __nv_bfloat16 g_wql[INNER * DIM];
__device__ __nv_bfloat16 g_wkvh[2 * INNER * DIM_VIS]; // Wkv^T [2048, 1024]
__device__ __nv_bfloat16 g_wkvl[2 * INNER * DIM_VIS];
__device__ __nv_bfloat16 g_woh[DIM * INNER];          // Wo^T  [2048, 1024]
__device__ __nv_bfloat16 g_wol[DIM * INNER];
__device__ float g_q [MTOT * INNER];
__device__ float g_kv[BB * J_TOT * 2 * INNER];
__device__ __nv_bfloat16 g_aoh[MTOT * INNER];
__device__ __nv_bfloat16 g_aol[MTOT * INNER];
__device__ int g_tt[MTOT];

// ================= helpers =================
__device__ __forceinline__ uint32_t smem_u32(const void* p) {
    uint32_t a;
    asm("{ .reg .u64 t; cvta.to.shared.u64 t, %1; cvt.u32.u64 %0, t; }" : "=r"(a) : "l"(p));
    return a;
}
__device__ __forceinline__ uint32_t lds32(uint32_t a) {
    uint32_t v;
    asm volatile("ld.shared.b32 %0, [%1];" : "=r"(v) : "r"(a));
    return v;
}
__device__ __forceinline__ void cp16(uint32_t d, const void* g) {
    asm volatile("cp.async.cg.shared.global [%0], [%1], 16;" :: "r"(d), "l"(g) : "memory");
}
__device__ __forceinline__ void cp_commit() { asm volatile("cp.async.commit_group;" ::: "memory"); }
template <int N> __device__ __forceinline__ void cp_wait() {
    asm volatile("cp.async.wait_group %0;" :: "n"(N) : "memory");
}
__device__ __forceinline__ void mma16816(float* c, const uint32_t* a, const uint32_t* b) {
    asm volatile("mma.sync.aligned.m16n8k16.row.col.f32.bf16.bf16.f32 "
        "{%0,%1,%2,%3}, {%4,%5,%6,%7}, {%8,%9}, {%0,%1,%2,%3};"
        : "+f"(c[0]), "+f"(c[1]), "+f"(c[2]), "+f"(c[3])
        : "r"(a[0]), "r"(a[1]), "r"(a[2]), "r"(a[3]), "r"(b[0]), "r"(b[1]));
}
// packed fp32x2 FMA (sm_100-family base PTX feature)
__device__ __forceinline__ void ffma2(unsigned long long& c, unsigned long long a, unsigned long long b) {
    asm("fma.rn.f32x2 %0, %1, %2, %0;" : "+l"(c) : "l"(a), "l"(b));
}
__device__ __forceinline__ unsigned long long pack2(float lo, float hi) {
    unsigned long long r;
    asm("mov.b64 %0, {%1, %2};" : "=l"(r) : "f"(lo), "f"(hi));
    return r;
}
__device__ __forceinline__ void unpack2(unsigned long long v, float& lo, float& hi) {
    asm("mov.b64 {%0, %1}, %2;" : "=f"(lo), "=f"(hi) : "l"(v));
}
__device__ __forceinline__ void split1(float v, __nv_bfloat16& h, __nv_bfloat16& l) {
    h = __float2bfloat16(v);
    l = __float2bfloat16(v - __bfloat162float(h));
}

// ---------------- text_time = cumsum(media_locations as 4-byte nonzero) ------
__global__ void cumsum_kernel(const unsigned int* __restrict__ ml) {
    __shared__ int seg[32];
    int b = blockIdx.x, t = threadIdx.x;
    const unsigned int* row = ml + b * T_TXT;
    int base = t * 64, local = 0;
    int pref[64];
    #pragma unroll 8
    for (int i = 0; i < 64; i++) { local += (row[base + i] != 0u) ? 1 : 0; pref[i] = local; }
    seg[t] = local;
    __syncwarp();
    int off = 0;
    for (int k = 0; k < t; k++) off += seg[k];
    int* out = g_tt + b * T_TXT + base;
    #pragma unroll 8
    for (int i = 0; i < 64; i++) out[i] = off + pref[i];
}

// ---------------- LayerNorm -> bf16 hi/lo ----------------
__global__ __launch_bounds__(256) void ln_kernel(const float* __restrict__ x,
                                                 const float* __restrict__ w,
                                                 const float* __restrict__ bb) {
    __shared__ float red[16];
    int row = blockIdx.x;
    const float* xr = x + (size_t)row * DIM;
    int base = threadIdx.x * 8;
    float4 a = *(const float4*)(xr + base);
    float4 c = *(const float4*)(xr + base + 4);
    float s  = a.x + a.y + a.z + a.w + c.x + c.y + c.z + c.w;
    float ss = a.x*a.x + a.y*a.y + a.z*a.z + a.w*a.w + c.x*c.x + c.y*c.y + c.z*c.z + c.w*c.w;
    #pragma unroll
    for (int o = 16; o > 0; o >>= 1) { s += __shfl_xor_sync(~0u, s, o); ss += __shfl_xor_sync(~0u, ss, o); }
    int warp = threadIdx.x >> 5, lane = threadIdx.x & 31;
    if (lane == 0) { red[warp] = s; red[warp + 8] = ss; }
    __syncthreads();
    s = 0.f; ss = 0.f;
    #pragma unroll
    for (int i = 0; i < 8; i++) { s += red[i]; ss += red[i + 8]; }
    float mu = s * (1.f / DIM);
    float r  = rsqrtf(ss * (1.f / DIM) - mu * mu + LN_EPS);

    float4 w0 = *(const float4*)(w + base), w1 = *(const float4*)(w + base + 4);
    float4 b0 = *(const float4*)(bb + base), b1 = *(const float4*)(bb + base + 4);
    float y[8];
    y[0]=(a.x-mu)*r*w0.x+b0.x; y[1]=(a.y-mu)*r*w0.y+b0.y; y[2]=(a.z-mu)*r*w0.z+b0.z; y[3]=(a.w-mu)*r*w0.w+b0.w;
    y[4]=(c.x-mu)*r*w1.x+b1.x; y[5]=(c.y-mu)*r*w1.y+b1.y; y[6]=(c.z-mu)*r*w1.z+b1.z; y[7]=(c.w-mu)*r*w1.w+b1.w;

    __align__(16) __nv_bfloat16 h[8], l[8];
    #pragma unroll
    for (int i = 0; i < 8; i++) split1(y[i], h[i], l[i]);
    size_t o = (size_t)row * DIM + base;
    *(uint4*)(g_xnh + o) = *(uint4*)h;
    *(uint4*)(g_xnl + o) = *(uint4*)l;
}

// ---------------- media fp32 -> hi/lo ----------------
__global__ __launch_bounds__(256) void split_kernel(const float* __restrict__ src,
                                                    __nv_bfloat16* __restrict__ dh,
                                                    __nv_bfloat16* __restrict__ dl) {
    int i = (blockIdx.x * 256 + threadIdx.x) * 4;
    float4 v = *(const float4*)(src + i);
    __align__(8) __nv_bfloat16 h[4], l[4];
    split1(v.x, h[0], l[0]); split1(v.y, h[1], l[1]);
    split1(v.z, h[2], l[2]); split1(v.w, h[3], l[3]);
    *(uint2*)(dh + i) = *(uint2*)h;
    *(uint2*)(dl + i) = *(uint2*)l;
}

// ---------------- weight transpose + split: W[K,N] -> Wt[N,K] hi/lo ----------
__global__ __launch_bounds__(256) void tsplit_kernel(const float* __restrict__ W,
                                                     __nv_bfloat16* __restrict__ Th,
                                                     __nv_bfloat16* __restrict__ Tl,
                                                     int K, int N) {
    __shared__ float t[32][33];
    int k0 = blockIdx.y * 32, n0 = blockIdx.x * 32;
    int tx = threadIdx.x & 31, ty = threadIdx.x >> 5;
    #pragma unroll
    for (int j = 0; j < 32; j += 8)
        t[ty + j][tx] = W[(size_t)(k0 + ty + j) * N + n0 + tx];
    __syncthreads();
    #pragma unroll
    for (int j = 0; j < 32; j += 8) {
        float v = t[tx][ty + j];
        __nv_bfloat16 h, l; split1(v, h, l);
        size_t o = (size_t)(n0 + ty + j) * K + k0 + tx;
        Th[o] = h; Tl[o] = l;
    }
}

// ============== HMMA split-bf16 GEMM core (R9 mainloop, proven 852) ==========
#define SST 40                    // smem row stride in bf16 (80 bytes)
#define ARR_B (128 * SST * 2)     // 10240 bytes per array
#define STAGE_B (4 * ARR_B)       // 40960
#define HG_SMEM (2 * STAGE_B)     // 81920

__device__ __forceinline__ void gemm_body(uint32_t sb,
                                          const __nv_bfloat16* Ah_, const __nv_bfloat16* Al_,
                                          const __nv_bfloat16* Bh_, const __nv_bfloat16* Bl_,
                                          float* C, int N, int K, int bm, int bn) {
    int tid = threadIdx.x, lane = tid & 31, wid = tid >> 5;
    int wm = wid >> 1, wn = wid & 1;      // warp grid 4x2

    const __nv_bfloat16* srcs[4] = {
        Ah_ + (size_t)bm * 128 * K, Al_ + (size_t)bm * 128 * K,
        Bh_ + (size_t)bn * 128 * K, Bl_ + (size_t)bn * 128 * K };

    int r0 = lane >> 2;            // 0..7
    int c0 = (lane & 3) * 2;       // 0,2,4,6

    float acc[2][8][4];
    #pragma unroll
    for (int mt = 0; mt < 2; mt++)
        #pragma unroll
        for (int nt = 0; nt < 8; nt++)
            #pragma unroll
            for (int q = 0; q < 4; q++) acc[mt][nt][q] = 0.f;

    int nchunk = K >> 5;

    auto load_chunk = [&](int c, int s) {
        uint32_t sbase = sb + s * STAGE_B;
        #pragma unroll
        for (int arr = 0; arr < 4; arr++) {
            #pragma unroll
            for (int i = 0; i < 2; i++) {
                int o = tid + 256 * i;          // 0..511
                int row = o >> 2, seg = o & 3;
                const void* g = srcs[arr] + (size_t)row * K + c * 32 + seg * 8;
                cp16(sbase + arr * ARR_B + row * (SST * 2) + seg * 16, g);
            }
        }
    };

    load_chunk(0, 0);
    cp_commit();

    for (int c = 0; c < nchunk; c++) {
        if (c + 1 < nchunk) { load_chunk(c + 1, (c + 1) & 1); cp_commit(); cp_wait<1>(); }
        else cp_wait<0>();
        __syncthreads();

        uint32_t st = sb + (c & 1) * STAGE_B;
        uint32_t Ahb = st, Alb = st + ARR_B, Bhb = st + 2 * ARR_B, Blb = st + 3 * ARR_B;

        #pragma unroll
        for (int ks = 0; ks < 2; ks++) {
            int k0 = ks * 16;
            uint32_t ah[2][4], al[2][4];
            #pragma unroll
            for (int mt = 0; mt < 2; mt++) {
                uint32_t ro = (uint32_t)((wm * 32 + mt * 16 + r0) * (SST * 2) + (k0 + c0) * 2);
                ah[mt][0] = lds32(Ahb + ro);
                ah[mt][1] = lds32(Ahb + ro + 8 * (SST * 2));
                ah[mt][2] = lds32(Ahb + ro + 16);
                ah[mt][3] = lds32(Ahb + ro + 8 * (SST * 2) + 16);
                al[mt][0] = lds32(Alb + ro);
                al[mt][1] = lds32(Alb + ro + 8 * (SST * 2));
                al[mt][2] = lds32(Alb + ro + 16);
                al[mt][3] = lds32(Alb + ro + 8 * (SST * 2) + 16);
            }
            #pragma unroll
            for (int nt = 0; nt < 8; nt++) {
                uint32_t no = (uint32_t)((wn * 64 + nt * 8 + r0) * (SST * 2) + (k0 + c0) * 2);
                uint32_t bh[2], bl[2];
                bh[0] = lds32(Bhb + no);
                bh[1] = lds32(Bhb + no + 16);
                bl[0] = lds32(Blb + no);
                bl[1] = lds32(Blb + no + 16);
                mma16816(acc[0][nt], ah[0], bh);
                mma16816(acc[1][nt], ah[1], bh);
                mma16816(acc[0][nt], ah[0], bl);
                mma16816(acc[1][nt], ah[1], bl);
                mma16816(acc[0][nt], al[0], bh);
                mma16816(acc[1][nt], al[1], bh);
            }
        }
        __syncthreads();
    }

    #pragma unroll
    for (int mt = 0; mt < 2; mt++) {
        int row = bm * 128 + wm * 32 + mt * 16 + r0;
        #pragma unroll
        for (int nt = 0; nt < 8; nt++) {
            int col = bn * 128 + wn * 64 + nt * 8 + c0;
            float* p = C + (size_t)row * N + col;
            *(float2*)p             = make_float2(acc[mt][nt][0], acc[mt][nt][1]);
            *(float2*)(p + 8 * N)   = make_float2(acc[mt][nt][2], acc[mt][nt][3]);
        }
    }
}

// Combined Q+KV GEMM: 512 Q tiles + 256 KV tiles in ONE launch (wave packing).
#define Q_TILES 512    // (8192/128) x (1024/128) = 64 x 8
#define KV_TILES 256   // (2048/128) x (2048/128) = 16 x 16

__global__ __launch_bounds__(256, 2) void hgemm_qkv() {
    extern __shared__ __align__(16) char smem[];
    uint32_t sb = smem_u32(smem);
    int id = blockIdx.x;
    if (id < Q_TILES) {
        // Q = xn @ Wq^T : M=8192, N=1024, K=2048 ; bm in [0,64), bn in [0,8)
        int bm = id >> 3, bn = id & 7;
        gemm_body(sb, g_xnh, g_xnl, g_wqh, g_wql, g_q, INNER, DIM, bm, bn);
    } else {
        // KV = media @ Wkv^T : M=2048, N=2048, K=1024 ; bm in [0,16), bn in [0,16)
        int t = id - Q_TILES;
        int bm = t >> 4, bn = t & 15;
        gemm_body(sb, g_mh, g_ml, g_wkvh, g_wkvl, g_kv, 2 * INNER, DIM_VIS, bm, bn);
    }
}

// Generic GEMM for the output projection.
__global__ __launch_bounds__(256, 2) void hgemm(const __nv_bfloat16* __restrict__ Ah_,
                                                const __nv_bfloat16* __restrict__ Al_,
                                                const __nv_bfloat16* __restrict__ Bh_,
                                                const __nv_bfloat16* __restrict__ Bl_,
                                                float* __restrict__ C,
                                                int M, int N, int K) {
    extern __shared__ __align__(16) char smem[];
    uint32_t sb = smem_u32(smem);
    gemm_body(sb, Ah_, Al_, Bh_, Bl_, C, N, K, blockIdx.y, blockIdx.x);
}

// ---------------- attention: packed f32x2, K transposed in smem -------------
__device__ __forceinline__ void attn_scalar(const float* __restrict__ qrow,
                                            const float* kb_, const float* vb_,
                                            int ld, __nv_bfloat16* __restrict__ oh,
                                            __nv_bfloat16* __restrict__ ol) {
    float sc[64];
    #pragma unroll
    for (int j = 0; j < 64; j++) sc[j] = 0.f;
    for (int d0 = 0; d0 < 64; d0 += 4) {
        float4 qv = *(const float4*)(qrow + d0);
        #pragma unroll
        for (int j = 0; j < 64; j++) {
            float4 kv = *(const float4*)(kb_ + j * ld + d0);
            sc[j] += qv.x * kv.x + qv.y * kv.y + qv.z * kv.z + qv.w * kv.w;
        }
    }
    float m = sc[0];
    #pragma unroll
    for (int j = 1; j < 64; j++) m = fmaxf(m, sc[j]);
    float sum = 0.f;
    #pragma unroll
    for (int j = 0; j < 64; j++) { float p = __expf((sc[j] - m) * 0.125f); sc[j] = p; sum += p; }
    float inv = 1.f / sum;
    #pragma unroll
    for (int j = 0; j < 64; j++) sc[j] *= inv;
    for (int d0 = 0; d0 < 64; d0 += 4) {
        float o[4] = {0.f, 0.f, 0.f, 0.f};
        #pragma unroll
        for (int j = 0; j < 64; j++) {
            float4 vv = *(const float4*)(vb_ + j * ld + d0);
            o[0] += sc[j] * vv.x; o[1] += sc[j] * vv.y;
            o[2] += sc[j] * vv.z; o[3] += sc[j] * vv.w;
        }
        __align__(8) __nv_bfloat16 h[4], l[4];
        #pragma unroll
        for (int j = 0; j < 4; j++) split1(o[j], h[j], l[j]);
        *(uint2*)(oh + d0) = *(uint2*)h;
        *(uint2*)(ol + d0) = *(uint2*)l;
    }
}

__global__ __launch_bounds__(256) void attn_kernel() {
    __shared__ float KsT[64][68];                 // [d][j], padded
    __shared__ __align__(16) float Vs[64][64];    // [j][d]
    int s = blockIdx.x, h = blockIdx.y, b = blockIdx.z;
    int tid = threadIdx.x;
    int i = s * 256 + tid;

    int tt0 = g_tt[b * T_TXT + s * 256];
    int kb0 = tt0 - 1;
    if (kb0 < 0) kb0 = 0;
    if (kb0 > T_IMG - 1) kb0 = T_IMG - 1;

    const float* kvsrc = g_kv + ((size_t)(b * J_TOT + kb0 * 64)) * (2 * INNER) + h * DIM_HEAD;
    for (int idx = tid; idx < 1024; idx += 256) {
        int j = idx >> 4, d0 = (idx & 15) * 4;
        float4 kk = *(const float4*)(kvsrc + (size_t)j * (2 * INNER) + d0);
        KsT[d0][j] = kk.x; KsT[d0 + 1][j] = kk.y; KsT[d0 + 2][j] = kk.z; KsT[d0 + 3][j] = kk.w;
        *(float4*)(&Vs[j][d0]) = *(const float4*)(kvsrc + (size_t)j * (2 * INNER) + INNER + d0);
    }
    __syncthreads();

    int t = g_tt[b * T_TXT + i];
    size_t obase = (size_t)(b * T_TXT + i) * INNER + h * DIM_HEAD;
    __nv_bfloat16* oh = g_aoh + obase;
    __nv_bfloat16* ol = g_aol + obase;
    if (t == 0) {
        #pragma unroll
        for (int d0 = 0; d0 < 64; d0 += 4) {
            *(uint2*)(oh + d0) = make_uint2(0u, 0u);
            *(uint2*)(ol + d0) = make_uint2(0u, 0u);
        }
        return;
    }
    int kb = t - 1;
    const float* qrow = g_q + (size_t)(b * T_TXT + i) * INNER + h * DIM_HEAD;
    if (kb != kb0) {   // correctness fallback (not taken for the given inputs)
        const float* kg = g_kv + ((size_t)(b * J_TOT + kb * 64)) * (2 * INNER) + h * DIM_HEAD;
        attn_scalar(qrow, kg, kg + INNER, 2 * INNER, oh, ol);
        return;
    }

    // ---- QK^T: packed over j-pairs ----
    unsigned long long sc2[32];
    #pragma unroll
    for (int j = 0; j < 32; j++) sc2[j] = 0ull;
    for (int d0 = 0; d0 < 64; d0 += 4) {
        float4 q4 = *(const float4*)(qrow + d0);
        float qa[4] = {q4.x, q4.y, q4.z, q4.w};
        #pragma unroll
        for (int dd = 0; dd < 4; dd++) {
            unsigned long long qq = pack2(qa[dd], qa[dd]);
            const float* krow = &KsT[d0 + dd][0];
            #pragma unroll
            for (int j4 = 0; j4 < 16; j4++) {
                ulonglong2 kk = *(const ulonglong2*)(krow + j4 * 4);
                ffma2(sc2[2 * j4],     qq, kk.x);
                ffma2(sc2[2 * j4 + 1], qq, kk.y);
            }
        }
    }

    // ---- softmax ----
    float sc[64];
    #pragma unroll
    for (int j = 0; j < 32; j++) unpack2(sc2[j], sc[2 * j], sc[2 * j + 1]);
    float m = sc[0];
    #pragma unroll
    for (int j = 1; j < 64; j++) m = fmaxf(m, sc[j]);
    float sum = 0.f;
    #pragma unroll
    for (int j = 0; j < 64; j++) { float p = __expf((sc[j] - m) * 0.125f); sc[j] = p; sum += p; }
    float inv = 1.f / sum;
    #pragma unroll
    for (int j = 0; j < 64; j++) sc[j] *= inv;

    // ---- P @ V: packed over d-pairs ----
    unsigned long long o2[32];
    #pragma unroll
    for (int d = 0; d < 32; d++) o2[d] = 0ull;
    for (int j = 0; j < 64; j++) {
        unsigned long long pp = pack2(sc[j], sc[j]);
        const float* vrow = &Vs[j][0];
        #pragma unroll
        for (int d4 = 0; d4 < 16; d4++) {
            ulonglong2 vv = *(const ulonglong2*)(vrow + d4 * 4);
            ffma2(o2[2 * d4],     pp, vv.x);
            ffma2(o2[2 * d4 + 1], pp, vv.y);
        }
    }

    #pragma unroll
    for (int d4 = 0; d4 < 16; d4++) {
        float o[4];
        unpack2(o2[2 * d4], o[0], o[1]);
        unpack2(o2[2 * d4 + 1], o[2], o[3]);
        __align__(8) __nv_bfloat16 hh[4], ll[4];
        #pragma unroll
        for (int q = 0; q < 4; q++) split1(o[q], hh[q], ll[q]);
        *(uint2*)(oh + d4 * 4) = *(uint2*)hh;
        *(uint2*)(ol + d4 * 4) = *(uint2*)ll;
    }
}

// ---------------- launch ----------------
extern "C" void kernel_launch(void* const* d_in, const int* in_sizes, int n_in,
                              void* d_out, int out_size) {
    const float* x     = (const float*)d_in[0];
    const float* media = (const float*)d_in[1];
    const float* nw    = (const float*)d_in[2];
    const float* nb    = (const float*)d_in[3];
    const float* Wq    = (const float*)d_in[4];
    const float* Wkv   = (const float*)d_in[5];
    const float* Wo    = (const float*)d_in[6];
    const unsigned int* ml = (const unsigned int*)d_in[7];
    float* out = (float*)d_out;

    cudaFuncSetAttribute(hgemm, cudaFuncAttributeMaxDynamicSharedMemorySize, HG_SMEM);
    cudaFuncSetAttribute(hgemm_qkv, cudaFuncAttributeMaxDynamicSharedMemorySize, HG_SMEM);

    void *p_mh, *p_ml, *p_wqh, *p_wql, *p_wkvh, *p_wkvl, *p_woh, *p_wol, *p_aoh, *p_aol;
    cudaGetSymbolAddress(&p_mh, g_mh);    cudaGetSymbolAddress(&p_ml, g_ml);
    cudaGetSymbolAddress(&p_wqh, g_wqh);  cudaGetSymbolAddress(&p_wql, g_wql);
    cudaGetSymbolAddress(&p_wkvh, g_wkvh);cudaGetSymbolAddress(&p_wkvl, g_wkvl);
    cudaGetSymbolAddress(&p_woh, g_woh);  cudaGetSymbolAddress(&p_wol, g_wol);
    cudaGetSymbolAddress(&p_aoh, g_aoh);  cudaGetSymbolAddress(&p_aol, g_aol);

    cumsum_kernel<<<BB, 32>>>(ml);
    ln_kernel<<<MTOT, 256>>>(x, nw, nb);
    split_kernel<<<(BB * J_TOT * DIM_VIS) / 1024, 256>>>(media, (__nv_bfloat16*)p_mh, (__nv_bfloat16*)p_ml);
    tsplit_kernel<<<dim3(INNER / 32, DIM / 32), 256>>>(Wq, (__nv_bfloat16*)p_wqh, (__nv_bfloat16*)p_wql, DIM, INNER);
    tsplit_kernel<<<dim3(2 * INNER / 32, DIM_VIS / 32), 256>>>(Wkv, (__nv_bfloat16*)p_wkvh, (__nv_bfloat16*)p_wkvl, DIM_VIS, 2 * INNER);
    tsplit_kernel<<<dim3(DIM / 32, INNER / 32), 256>>>(Wo, (__nv_bfloat16*)p_woh, (__nv_bfloat16*)p_wol, INNER, DIM);

    // Q + KV in one launch (768 CTAs, wave packing at 2 CTAs/SM)
    hgemm_qkv<<<Q_TILES + KV_TILES, 256, HG_SMEM>>>();

    attn_kernel<<<dim3(T_TXT / 256, HEADS, BB), 256>>>();

    // out = ao @ Wo : M=8192, N=2048, K=1024
    hgemm<<<dim3(DIM / 128, MTOT / 128), 256, HG_SMEM>>>(
        (const __nv_bfloat16*)p_aoh, (const __nv_bfloat16*)p_aol,
        (const __nv_bfloat16*)p_woh, (const __nv_bfloat16*)p_wol,
        out, MTOT, DIM, INNER);
}

// round 15
// speedup vs baseline: 1.1114x; 1.0259x over previous
#include <cuda_runtime.h>
#include <cuda_bf16.h>
#include <cstdint>
#include <math.h>

#define BB 4
#define T_TXT 2048
#define DIM 2048
#define T_IMG 8
#define N_LAT 64
#define DIM_VIS 1024
#define HEADS 16
#define DIM_HEAD 64
#define INNER 1024
#define J_TOT (T_IMG * N_LAT)   // 512
#define LN_EPS 1e-5f
#define MTOT (BB * T_TXT)       // 8192

// ---------------- scratch (static device globals; no allocation) ----------------
__device__ __nv_bfloat16 g_xnh[MTOT * DIM];
__device__ __nv_bfloat16 g_xnl[MTOT * DIM];
__device__ __nv_bfloat16 g_mh [BB * J_TOT * DIM_VIS];
__device__ __nv_bfloat16 g_ml [BB * J_TOT * DIM_VIS];
__device__ __nv_bfloat16 g_wqh[INNER * DIM];          // Wq^T  [1024, 2048]
__device__ __nv_bfloat16 g_wql[INNER * DIM];
__device__ __nv_bfloat16 g_wkvh[2 * INNER * DIM_VIS]; // Wkv^T [2048, 1024]
__device__ __nv_bfloat16 g_wkvl[2 * INNER * DIM_VIS];
__device__ __nv_bfloat16 g_woh[DIM * INNER];          // Wo^T  [2048, 1024]
__device__ __nv_bfloat16 g_wol[DIM * INNER];
__device__ float g_q [MTOT * INNER];
__device__ float g_kv[BB * J_TOT * 2 * INNER];
__device__ __nv_bfloat16 g_aoh[MTOT * INNER];
__device__ __nv_bfloat16 g_aol[MTOT * INNER];
__device__ int g_tt[MTOT];

// ================= helpers =================
__device__ __forceinline__ uint32_t smem_u32(const void* p) {
    uint32_t a;
    asm("{ .reg .u64 t; cvta.to.shared.u64 t, %1; cvt.u32.u64 %0, t; }" : "=r"(a) : "l"(p));
    return a;
}
__device__ __forceinline__ uint32_t lds32(uint32_t a) {
    uint32_t v;
    asm volatile("ld.shared.b32 %0, [%1];" : "=r"(v) : "r"(a));
    return v;
}
__device__ __forceinline__ void cp16(uint32_t d, const void* g) {
    asm volatile("cp.async.cg.shared.global [%0], [%1], 16;" :: "r"(d), "l"(g) : "memory");
}
__device__ __forceinline__ void cp_commit() { asm volatile("cp.async.commit_group;" ::: "memory"); }
template <int N> __device__ __forceinline__ void cp_wait() {
    asm volatile("cp.async.wait_group %0;" :: "n"(N) : "memory");
}
__device__ __forceinline__ void mma16816(float* c, const uint32_t* a, const uint32_t* b) {
    asm volatile("mma.sync.aligned.m16n8k16.row.col.f32.bf16.bf16.f32 "
        "{%0,%1,%2,%3}, {%4,%5,%6,%7}, {%8,%9}, {%0,%1,%2,%3};"
        : "+f"(c[0]), "+f"(c[1]), "+f"(c[2]), "+f"(c[3])
        : "r"(a[0]), "r"(a[1]), "r"(a[2]), "r"(a[3]), "r"(b[0]), "r"(b[1]));
}
// packed fp32x2 FMA (sm_100-family base PTX feature)
__device__ __forceinline__ void ffma2(unsigned long long& c, unsigned long long a, unsigned long long b) {
    asm("fma.rn.f32x2 %0, %1, %2, %0;" : "+l"(c) : "l"(a), "l"(b));
}
__device__ __forceinline__ unsigned long long pack2(float lo, float hi) {
    unsigned long long r;
    asm("mov.b64 %0, {%1, %2};" : "=l"(r) : "f"(lo), "f"(hi));
    return r;
}
__device__ __forceinline__ void unpack2(unsigned long long v, float& lo, float& hi) {
    asm("mov.b64 {%0, %1}, %2;" : "=f"(lo), "=f"(hi) : "l"(v));
}
__device__ __forceinline__ void split1(float v, __nv_bfloat16& h, __nv_bfloat16& l) {
    h = __float2bfloat16(v);
    l = __float2bfloat16(v - __bfloat162float(h));
}

// ================= fused pre-processing kernel =================
// Block ranges (all independent):
//   [0, 8192)            : LayerNorm row -> xn hi/lo
//   [8192, 10240)        : media fp32 -> hi/lo (1024 floats per block)
//   [10240, 12288)       : tsplit Wq   (K=2048, N=1024)
//   [12288, 14336)       : tsplit Wkv  (K=1024, N=2048)
//   [14336, 16384)       : tsplit Wo   (K=1024, N=2048)
//   [16384, 16388)       : cumsum (batch = id - 16384)
#define PREP_LN0    0
#define PREP_SPL0   8192
#define PREP_WQ0    10240
#define PREP_WKV0   12288
#define PREP_WO0    14336
#define PREP_CUM0   16384
#define PREP_BLOCKS 16388

__device__ __forceinline__ void tsplit_body(const float* __restrict__ W,
                                            __nv_bfloat16* __restrict__ Th,
                                            __nv_bfloat16* __restrict__ Tl,
                                            int K, int N, int bx, int by,
                                            float (*t)[33]) {
    int k0 = by * 32, n0 = bx * 32;
    int tx = threadIdx.x & 31, ty = threadIdx.x >> 5;
    #pragma unroll
    for (int j = 0; j < 32; j += 8)
        t[ty + j][tx] = W[(size_t)(k0 + ty + j) * N + n0 + tx];
    __syncthreads();
    #pragma unroll
    for (int j = 0; j < 32; j += 8) {
        float v = t[tx][ty + j];
        __nv_bfloat16 h, l; split1(v, h, l);
        size_t o = (size_t)(n0 + ty + j) * K + k0 + tx;
        Th[o] = h; Tl[o] = l;
    }
}

__global__ __launch_bounds__(256) void prep_kernel(const float* __restrict__ x,
                                                   const float* __restrict__ w,
                                                   const float* __restrict__ bb,
                                                   const float* __restrict__ media,
                                                   const float* __restrict__ Wq,
                                                   const float* __restrict__ Wkv,
                                                   const float* __restrict__ Wo,
                                                   const unsigned int* __restrict__ ml) {
    __shared__ float red[16];
    __shared__ float tbuf[32][33];
    __shared__ int seg[32];

    int id = blockIdx.x;

    if (id < PREP_SPL0) {
        // ---- LayerNorm ----
        int row = id;
        const float* xr = x + (size_t)row * DIM;
        int base = threadIdx.x * 8;
        float4 a = *(const float4*)(xr + base);
        float4 c = *(const float4*)(xr + base + 4);
        float s  = a.x + a.y + a.z + a.w + c.x + c.y + c.z + c.w;
        float ss = a.x*a.x + a.y*a.y + a.z*a.z + a.w*a.w + c.x*c.x + c.y*c.y + c.z*c.z + c.w*c.w;
        #pragma unroll
        for (int o = 16; o > 0; o >>= 1) { s += __shfl_xor_sync(~0u, s, o); ss += __shfl_xor_sync(~0u, ss, o); }
        int warp = threadIdx.x >> 5, lane = threadIdx.x & 31;
        if (lane == 0) { red[warp] = s; red[warp + 8] = ss; }
        __syncthreads();
        s = 0.f; ss = 0.f;
        #pragma unroll
        for (int i = 0; i < 8; i++) { s += red[i]; ss += red[i + 8]; }
        float mu = s * (1.f / DIM);
        float r  = rsqrtf(ss * (1.f / DIM) - mu * mu + LN_EPS);

        float4 w0 = *(const float4*)(w + base), w1 = *(const float4*)(w + base + 4);
        float4 b0 = *(const float4*)(bb + base), b1 = *(const float4*)(bb + base + 4);
        float y[8];
        y[0]=(a.x-mu)*r*w0.x+b0.x; y[1]=(a.y-mu)*r*w0.y+b0.y; y[2]=(a.z-mu)*r*w0.z+b0.z; y[3]=(a.w-mu)*r*w0.w+b0.w;
        y[4]=(c.x-mu)*r*w1.x+b1.x; y[5]=(c.y-mu)*r*w1.y+b1.y; y[6]=(c.z-mu)*r*w1.z+b1.z; y[7]=(c.w-mu)*r*w1.w+b1.w;

        __align__(16) __nv_bfloat16 h[8], l[8];
        #pragma unroll
        for (int i = 0; i < 8; i++) split1(y[i], h[i], l[i]);
        size_t o = (size_t)row * DIM + base;
        *(uint4*)(g_xnh + o) = *(uint4*)h;
        *(uint4*)(g_xnl + o) = *(uint4*)l;
    } else if (id < PREP_WQ0) {
        // ---- media split ----
        int i = ((id - PREP_SPL0) * 256 + threadIdx.x) * 4;
        float4 v = *(const float4*)(media + i);
        __align__(8) __nv_bfloat16 h[4], l[4];
        split1(v.x, h[0], l[0]); split1(v.y, h[1], l[1]);
        split1(v.z, h[2], l[2]); split1(v.w, h[3], l[3]);
        *(uint2*)(g_mh + i) = *(uint2*)h;
        *(uint2*)(g_ml + i) = *(uint2*)l;
    } else if (id < PREP_WKV0) {
        // ---- tsplit Wq: K=2048, N=1024, grid (32 x 64) ----
        int t = id - PREP_WQ0;
        tsplit_body(Wq, g_wqh, g_wql, DIM, INNER, t & 31, t >> 5, tbuf);
    } else if (id < PREP_WO0) {
        // ---- tsplit Wkv: K=1024, N=2048, grid (64 x 32) ----
        int t = id - PREP_WKV0;
        tsplit_body(Wkv, g_wkvh, g_wkvl, DIM_VIS, 2 * INNER, t & 63, t >> 6, tbuf);
    } else if (id < PREP_CUM0) {
        // ---- tsplit Wo: K=1024, N=2048, grid (64 x 32) ----
        int t = id - PREP_WO0;
        tsplit_body(Wo, g_woh, g_wol, INNER, DIM, t & 63, t >> 6, tbuf);
    } else {
        // ---- cumsum (first warp only) ----
        int b = id - PREP_CUM0;
        int t = threadIdx.x;
        if (t < 32) {
            const unsigned int* row = ml + b * T_TXT;
            int base = t * 64, local = 0;
            int pref[64];
            #pragma unroll 8
            for (int i = 0; i < 64; i++) { local += (row[base + i] != 0u) ? 1 : 0; pref[i] = local; }
            seg[t] = local;
            __syncwarp();
            int off = 0;
            for (int k = 0; k < t; k++) off += seg[k];
            int* out = g_tt + b * T_TXT + base;
            #pragma unroll 8
            for (int i = 0; i < 64; i++) out[i] = off + pref[i];
        }
    }
}

// ============== HMMA split-bf16 GEMM core (R9 mainloop, proven 852) ==========
#define SST 40                    // smem row stride in bf16 (80 bytes)
#define ARR_B (128 * SST * 2)     // 10240 bytes per array
#define STAGE_B (4 * ARR_B)       // 40960
#define HG_SMEM (2 * STAGE_B)     // 81920

__device__ __forceinline__ void gemm_body(uint32_t sb,
                                          const __nv_bfloat16* Ah_, const __nv_bfloat16* Al_,
                                          const __nv_bfloat16* Bh_, const __nv_bfloat16* Bl_,
                                          float* C, int N, int K, int bm, int bn) {
    int tid = threadIdx.x, lane = tid & 31, wid = tid >> 5;
    int wm = wid >> 1, wn = wid & 1;      // warp grid 4x2

    const __nv_bfloat16* srcs[4] = {
        Ah_ + (size_t)bm * 128 * K, Al_ + (size_t)bm * 128 * K,
        Bh_ + (size_t)bn * 128 * K, Bl_ + (size_t)bn * 128 * K };

    int r0 = lane >> 2;            // 0..7
    int c0 = (lane & 3) * 2;       // 0,2,4,6

    float acc[2][8][4];
    #pragma unroll
    for (int mt = 0; mt < 2; mt++)
        #pragma unroll
        for (int nt = 0; nt < 8; nt++)
            #pragma unroll
            for (int q = 0; q < 4; q++) acc[mt][nt][q] = 0.f;

    int nchunk = K >> 5;

    auto load_chunk = [&](int c, int s) {
        uint32_t sbase = sb + s * STAGE_B;
        #pragma unroll
        for (int arr = 0; arr < 4; arr++) {
            #pragma unroll
            for (int i = 0; i < 2; i++) {
                int o = tid + 256 * i;          // 0..511
                int row = o >> 2, seg = o & 3;
                const void* g = srcs[arr] + (size_t)row * K + c * 32 + seg * 8;
                cp16(sbase + arr * ARR_B + row * (SST * 2) + seg * 16, g);
            }
        }
    };

    load_chunk(0, 0);
    cp_commit();

    for (int c = 0; c < nchunk; c++) {
        if (c + 1 < nchunk) { load_chunk(c + 1, (c + 1) & 1); cp_commit(); cp_wait<1>(); }
        else cp_wait<0>();
        __syncthreads();

        uint32_t st = sb + (c & 1) * STAGE_B;
        uint32_t Ahb = st, Alb = st + ARR_B, Bhb = st + 2 * ARR_B, Blb = st + 3 * ARR_B;

        #pragma unroll
        for (int ks = 0; ks < 2; ks++) {
            int k0 = ks * 16;
            uint32_t ah[2][4], al[2][4];
            #pragma unroll
            for (int mt = 0; mt < 2; mt++) {
                uint32_t ro = (uint32_t)((wm * 32 + mt * 16 + r0) * (SST * 2) + (k0 + c0) * 2);
                ah[mt][0] = lds32(Ahb + ro);
                ah[mt][1] = lds32(Ahb + ro + 8 * (SST * 2));
                ah[mt][2] = lds32(Ahb + ro + 16);
                ah[mt][3] = lds32(Ahb + ro + 8 * (SST * 2) + 16);
                al[mt][0] = lds32(Alb + ro);
                al[mt][1] = lds32(Alb + ro + 8 * (SST * 2));
                al[mt][2] = lds32(Alb + ro + 16);
                al[mt][3] = lds32(Alb + ro + 8 * (SST * 2) + 16);
            }
            #pragma unroll
            for (int nt = 0; nt < 8; nt++) {
                uint32_t no = (uint32_t)((wn * 64 + nt * 8 + r0) * (SST * 2) + (k0 + c0) * 2);
                uint32_t bh[2], bl[2];
                bh[0] = lds32(Bhb + no);
                bh[1] = lds32(Bhb + no + 16);
                bl[0] = lds32(Blb + no);
                bl[1] = lds32(Blb + no + 16);
                mma16816(acc[0][nt], ah[0], bh);
                mma16816(acc[1][nt], ah[1], bh);
                mma16816(acc[0][nt], ah[0], bl);
                mma16816(acc[1][nt], ah[1], bl);
                mma16816(acc[0][nt], al[0], bh);
                mma16816(acc[1][nt], al[1], bh);
            }
        }
        __syncthreads();
    }

    #pragma unroll
    for (int mt = 0; mt < 2; mt++) {
        int row = bm * 128 + wm * 32 + mt * 16 + r0;
        #pragma unroll
        for (int nt = 0; nt < 8; nt++) {
            int col = bn * 128 + wn * 64 + nt * 8 + c0;
            float* p = C + (size_t)row * N + col;
            *(float2*)p             = make_float2(acc[mt][nt][0], acc[mt][nt][1]);
            *(float2*)(p + 8 * N)   = make_float2(acc[mt][nt][2], acc[mt][nt][3]);
        }
    }
}

// Combined Q+KV GEMM: 512 Q tiles + 256 KV tiles in ONE launch (wave packing).
#define Q_TILES 512    // (8192/128) x (1024/128) = 64 x 8
#define KV_TILES 256   // (2048/128) x (2048/128) = 16 x 16

__global__ __launch_bounds__(256, 2) void hgemm_qkv() {
    extern __shared__ __align__(16) char smem[];
    uint32_t sb = smem_u32(smem);
    int id = blockIdx.x;
    if (id < Q_TILES) {
        int bm = id >> 3, bn = id & 7;
        gemm_body(sb, g_xnh, g_xnl, g_wqh, g_wql, g_q, INNER, DIM, bm, bn);
    } else {
        int t = id - Q_TILES;
        int bm = t >> 4, bn = t & 15;
        gemm_body(sb, g_mh, g_ml, g_wkvh, g_wkvl, g_kv, 2 * INNER, DIM_VIS, bm, bn);
    }
}

// Generic GEMM for the output projection.
__global__ __launch_bounds__(256, 2) void hgemm(const __nv_bfloat16* __restrict__ Ah_,
                                                const __nv_bfloat16* __restrict__ Al_,
                                                const __nv_bfloat16* __restrict__ Bh_,
                                                const __nv_bfloat16* __restrict__ Bl_,
                                                float* __restrict__ C,
                                                int M, int N, int K) {
    extern __shared__ __align__(16) char smem[];
    uint32_t sb = smem_u32(smem);
    gemm_body(sb, Ah_, Al_, Bh_, Bl_, C, N, K, blockIdx.y, blockIdx.x);
}

// ---------------- attention: packed f32x2, K transposed in smem -------------
__device__ __forceinline__ void attn_scalar(const float* __restrict__ qrow,
                                            const float* kb_, const float* vb_,
                                            int ld, __nv_bfloat16* __restrict__ oh,
                                            __nv_bfloat16* __restrict__ ol) {
    float sc[64];
    #pragma unroll
    for (int j = 0; j < 64; j++) sc[j] = 0.f;
    for (int d0 = 0; d0 < 64; d0 += 4) {
        float4 qv = *(const float4*)(qrow + d0);
        #pragma unroll
        for (int j = 0; j < 64; j++) {
            float4 kv = *(const float4*)(kb_ + j * ld + d0);
            sc[j] += qv.x * kv.x + qv.y * kv.y + qv.z * kv.z + qv.w * kv.w;
        }
    }
    float m = sc[0];
    #pragma unroll
    for (int j = 1; j < 64; j++) m = fmaxf(m, sc[j]);
    float sum = 0.f;
    #pragma unroll
    for (int j = 0; j < 64; j++) { float p = __expf((sc[j] - m) * 0.125f); sc[j] = p; sum += p; }
    float inv = 1.f / sum;
    #pragma unroll
    for (int j = 0; j < 64; j++) sc[j] *= inv;
    for (int d0 = 0; d0 < 64; d0 += 4) {
        float o[4] = {0.f, 0.f, 0.f, 0.f};
        #pragma unroll
        for (int j = 0; j < 64; j++) {
            float4 vv = *(const float4*)(vb_ + j * ld + d0);
            o[0] += sc[j] * vv.x; o[1] += sc[j] * vv.y;
            o[2] += sc[j] * vv.z; o[3] += sc[j] * vv.w;
        }
        __align__(8) __nv_bfloat16 h[4], l[4];
        #pragma unroll
        for (int j = 0; j < 4; j++) split1(o[j], h[j], l[j]);
        *(uint2*)(oh + d0) = *(uint2*)h;
        *(uint2*)(ol + d0) = *(uint2*)l;
    }
}

__global__ __launch_bounds__(256) void attn_kernel() {
    __shared__ float KsT[64][68];                 // [d][j], padded
    __shared__ __align__(16) float Vs[64][64];    // [j][d]
    int s = blockIdx.x, h = blockIdx.y, b = blockIdx.z;
    int tid = threadIdx.x;
    int i = s * 256 + tid;

    int tt0 = g_tt[b * T_TXT + s * 256];
    int kb0 = tt0 - 1;
    if (kb0 < 0) kb0 = 0;
    if (kb0 > T_IMG - 1) kb0 = T_IMG - 1;

    const float* kvsrc = g_kv + ((size_t)(b * J_TOT + kb0 * 64)) * (2 * INNER) + h * DIM_HEAD;
    for (int idx = tid; idx < 1024; idx += 256) {
        int j = idx >> 4, d0 = (idx & 15) * 4;
        float4 kk = *(const float4*)(kvsrc + (size_t)j * (2 * INNER) + d0);
        KsT[d0][j] = kk.x; KsT[d0 + 1][j] = kk.y; KsT[d0 + 2][j] = kk.z; KsT[d0 + 3][j] = kk.w;
        *(float4*)(&Vs[j][d0]) = *(const float4*)(kvsrc + (size_t)j * (2 * INNER) + INNER + d0);
    }
    __syncthreads();

    int t = g_tt[b * T_TXT + i];
    size_t obase = (size_t)(b * T_TXT + i) * INNER + h * DIM_HEAD;
    __nv_bfloat16* oh = g_aoh + obase;
    __nv_bfloat16* ol = g_aol + obase;
    if (t == 0) {
        #pragma unroll
        for (int d0 = 0; d0 < 64; d0 += 4) {
            *(uint2*)(oh + d0) = make_uint2(0u, 0u);
            *(uint2*)(ol + d0) = make_uint2(0u, 0u);
        }
        return;
    }
    int kb = t - 1;
    const float* qrow = g_q + (size_t)(b * T_TXT + i) * INNER + h * DIM_HEAD;
    if (kb != kb0) {   // correctness fallback (not taken for the given inputs)
        const float* kg = g_kv + ((size_t)(b * J_TOT + kb * 64)) * (2 * INNER) + h * DIM_HEAD;
        attn_scalar(qrow, kg, kg + INNER, 2 * INNER, oh, ol);
        return;
    }

    // ---- QK^T: packed over j-pairs ----
    unsigned long long sc2[32];
    #pragma unroll
    for (int j = 0; j < 32; j++) sc2[j] = 0ull;
    for (int d0 = 0; d0 < 64; d0 += 4) {
        float4 q4 = *(const float4*)(qrow + d0);
        float qa[4] = {q4.x, q4.y, q4.z, q4.w};
        #pragma unroll
        for (int dd = 0; dd < 4; dd++) {
            unsigned long long qq = pack2(qa[dd], qa[dd]);
            const float* krow = &KsT[d0 + dd][0];
            #pragma unroll
            for (int j4 = 0; j4 < 16; j4++) {
                ulonglong2 kk = *(const ulonglong2*)(krow + j4 * 4);
                ffma2(sc2[2 * j4],     qq, kk.x);
                ffma2(sc2[2 * j4 + 1], qq, kk.y);
            }
        }
    }

    // ---- softmax ----
    float sc[64];
    #pragma unroll
    for (int j = 0; j < 32; j++) unpack2(sc2[j], sc[2 * j], sc[2 * j + 1]);
    float m = sc[0];
    #pragma unroll
    for (int j = 1; j < 64; j++) m = fmaxf(m, sc[j]);
    float sum = 0.f;
    #pragma unroll
    for (int j = 0; j < 64; j++) { float p = __expf((sc[j] - m) * 0.125f); sc[j] = p; sum += p; }
    float inv = 1.f / sum;
    #pragma unroll
    for (int j = 0; j < 64; j++) sc[j] *= inv;

    // ---- P @ V: packed over d-pairs ----
    unsigned long long o2[32];
    #pragma unroll
    for (int d = 0; d < 32; d++) o2[d] = 0ull;
    for (int j = 0; j < 64; j++) {
        unsigned long long pp = pack2(sc[j], sc[j]);
        const float* vrow = &Vs[j][0];
        #pragma unroll
        for (int d4 = 0; d4 < 16; d4++) {
            ulonglong2 vv = *(const ulonglong2*)(vrow + d4 * 4);
            ffma2(o2[2 * d4],     pp, vv.x);
            ffma2(o2[2 * d4 + 1], pp, vv.y);
        }
    }

    #pragma unroll
    for (int d4 = 0; d4 < 16; d4++) {
        float o[4];
        unpack2(o2[2 * d4], o[0], o[1]);
        unpack2(o2[2 * d4 + 1], o[2], o[3]);
        __align__(8) __nv_bfloat16 hh[4], ll[4];
        #pragma unroll
        for (int q = 0; q < 4; q++) split1(o[q], hh[q], ll[q]);
        *(uint2*)(oh + d4 * 4) = *(uint2*)hh;
        *(uint2*)(ol + d4 * 4) = *(uint2*)ll;
    }
}

// ---------------- launch ----------------
extern "C" void kernel_launch(void* const* d_in, const int* in_sizes, int n_in,
                              void* d_out, int out_size) {
    const float* x     = (const float*)d_in[0];
    const float* media = (const float*)d_in[1];
    const float* nw    = (const float*)d_in[2];
    const float* nb    = (const float*)d_in[3];
    const float* Wq    = (const float*)d_in[4];
    const float* Wkv   = (const float*)d_in[5];
    const float* Wo    = (const float*)d_in[6];
    const unsigned int* ml = (const unsigned int*)d_in[7];
    float* out = (float*)d_out;

    cudaFuncSetAttribute(hgemm, cudaFuncAttributeMaxDynamicSharedMemorySize, HG_SMEM);
    cudaFuncSetAttribute(hgemm_qkv, cudaFuncAttributeMaxDynamicSharedMemorySize, HG_SMEM);

    void *p_aoh, *p_aol, *p_woh, *p_wol;
    cudaGetSymbolAddress(&p_aoh, g_aoh);  cudaGetSymbolAddress(&p_aol, g_aol);
    cudaGetSymbolAddress(&p_woh, g_woh);  cudaGetSymbolAddress(&p_wol, g_wol);

    // All pre-processing in ONE launch (ln + media split + 3 tsplits + cumsum)
    prep_kernel<<<PREP_BLOCKS, 256>>>(x, nw, nb, media, Wq, Wkv, Wo, ml);

    // Q + KV in one launch (768 CTAs, wave packing at 2 CTAs/SM)
    hgemm_qkv<<<Q_TILES + KV_TILES, 256, HG_SMEM>>>();

    attn_kernel<<<dim3(T_TXT / 256, HEADS, BB), 256>>>();

    // out = ao @ Wo : M=8192, N=2048, K=1024
    hgemm<<<dim3(DIM / 128, MTOT / 128), 256, HG_SMEM>>>(
        (const __nv_bfloat16*)p_aoh, (const __nv_bfloat16*)p_aol,
        (const __nv_bfloat16*)p_woh, (const __nv_bfloat16*)p_wol,
        out, MTOT, DIM, INNER);
}

// round 16
// speedup vs baseline: 1.1136x; 1.0020x over previous
#include <cuda_runtime.h>
#include <cuda_bf16.h>
#include <cstdint>
#include <math.h>

#define BB 4
#define T_TXT 2048
#define DIM 2048
#define T_IMG 8
#define N_LAT 64
#define DIM_VIS 1024
#define HEADS 16
#define DIM_HEAD 64
#define INNER 1024
#define J_TOT (T_IMG * N_LAT)   // 512
#define LN_EPS 1e-5f
#define MTOT (BB * T_TXT)       // 8192

// ---------------- scratch (static device globals; no allocation) ----------------
__device__ __nv_bfloat16 g_xnh[MTOT * DIM];
__device__ __nv_bfloat16 g_xnl[MTOT * DIM];
__device__ __nv_bfloat16 g_mh [BB * J_TOT * DIM_VIS];
__device__ __nv_bfloat16 g_ml [BB * J_TOT * DIM_VIS];
__device__ __nv_bfloat16 g_wqh[INNER * DIM];          // Wq^T  [1024, 2048]
__device__ __nv_bfloat16 g_wql[INNER * DIM];
__device__ __nv_bfloat16 g_wkvh[2 * INNER * DIM_VIS]; // Wkv^T [2048, 1024]
__device__ __nv_bfloat16 g_wkvl[2 * INNER * DIM_VIS];
__device__ __nv_bfloat16 g_woh[DIM * INNER];          // Wo^T  [2048, 1024]
__device__ __nv_bfloat16 g_wol[DIM * INNER];
__device__ float g_q [MTOT * INNER];
__device__ float g_kv[BB * J_TOT * 2 * INNER];
__device__ __nv_bfloat16 g_aoh[MTOT * INNER];
__device__ __nv_bfloat16 g_aol[MTOT * INNER];
__device__ int g_tt[MTOT];

// ================= helpers =================
__device__ __forceinline__ uint32_t smem_u32(const void* p) {
    uint32_t a;
    asm("{ .reg .u64 t; cvta.to.shared.u64 t, %1; cvt.u32.u64 %0, t; }" : "=r"(a) : "l"(p));
    return a;
}
__device__ __forceinline__ uint32_t lds32(uint32_t a) {
    uint32_t v;
    asm volatile("ld.shared.b32 %0, [%1];" : "=r"(v) : "r"(a));
    return v;
}
__device__ __forceinline__ void cp16(uint32_t d, const void* g) {
    asm volatile("cp.async.cg.shared.global [%0], [%1], 16;" :: "r"(d), "l"(g) : "memory");
}
__device__ __forceinline__ void cp_commit() { asm volatile("cp.async.commit_group;" ::: "memory"); }
template <int N> __device__ __forceinline__ void cp_wait() {
    asm volatile("cp.async.wait_group %0;" :: "n"(N) : "memory");
}
__device__ __forceinline__ void mma16816(float* c, const uint32_t* a, const uint32_t* b) {
    asm volatile("mma.sync.aligned.m16n8k16.row.col.f32.bf16.bf16.f32 "
        "{%0,%1,%2,%3}, {%4,%5,%6,%7}, {%8,%9}, {%0,%1,%2,%3};"
        : "+f"(c[0]), "+f"(c[1]), "+f"(c[2]), "+f"(c[3])
        : "r"(a[0]), "r"(a[1]), "r"(a[2]), "r"(a[3]), "r"(b[0]), "r"(b[1]));
}
// packed fp32x2 FMA (sm_100-family base PTX feature)
__device__ __forceinline__ void ffma2(unsigned long long& c, unsigned long long a, unsigned long long b) {
    asm("fma.rn.f32x2 %0, %1, %2, %0;" : "+l"(c) : "l"(a), "l"(b));
}
__device__ __forceinline__ unsigned long long pack2(float lo, float hi) {
    unsigned long long r;
    asm("mov.b64 %0, {%1, %2};" : "=l"(r) : "f"(lo), "f"(hi));
    return r;
}
__device__ __forceinline__ void unpack2(unsigned long long v, float& lo, float& hi) {
    asm("mov.b64 {%0, %1}, %2;" : "=f"(lo), "=f"(hi) : "l"(v));
}
__device__ __forceinline__ void split1(float v, __nv_bfloat16& h, __nv_bfloat16& l) {
    h = __float2bfloat16(v);
    l = __float2bfloat16(v - __bfloat162float(h));
}

// ================= fused pre-processing kernel =================
#define PREP_LN0    0
#define PREP_SPL0   8192
#define PREP_WQ0    10240
#define PREP_WKV0   12288
#define PREP_WO0    14336
#define PREP_CUM0   16384
#define PREP_BLOCKS 16388

__device__ __forceinline__ void tsplit_body(const float* __restrict__ W,
                                            __nv_bfloat16* __restrict__ Th,
                                            __nv_bfloat16* __restrict__ Tl,
                                            int K, int N, int bx, int by,
                                            float (*t)[33]) {
    int k0 = by * 32, n0 = bx * 32;
    int tx = threadIdx.x & 31, ty = threadIdx.x >> 5;
    #pragma unroll
    for (int j = 0; j < 32; j += 8)
        t[ty + j][tx] = W[(size_t)(k0 + ty + j) * N + n0 + tx];
    __syncthreads();
    #pragma unroll
    for (int j = 0; j < 32; j += 8) {
        float v = t[tx][ty + j];
        __nv_bfloat16 h, l; split1(v, h, l);
        size_t o = (size_t)(n0 + ty + j) * K + k0 + tx;
        Th[o] = h; Tl[o] = l;
    }
}

__global__ __launch_bounds__(256) void prep_kernel(const float* __restrict__ x,
                                                   const float* __restrict__ w,
                                                   const float* __restrict__ bb,
                                                   const float* __restrict__ media,
                                                   const float* __restrict__ Wq,
                                                   const float* __restrict__ Wkv,
                                                   const float* __restrict__ Wo,
                                                   const unsigned int* __restrict__ ml) {
    __shared__ float red[16];
    __shared__ float tbuf[32][33];
    __shared__ int seg[32];

    int id = blockIdx.x;

    if (id < PREP_SPL0) {
        int row = id;
        const float* xr = x + (size_t)row * DIM;
        int base = threadIdx.x * 8;
        float4 a = *(const float4*)(xr + base);
        float4 c = *(const float4*)(xr + base + 4);
        float s  = a.x + a.y + a.z + a.w + c.x + c.y + c.z + c.w;
        float ss = a.x*a.x + a.y*a.y + a.z*a.z + a.w*a.w + c.x*c.x + c.y*c.y + c.z*c.z + c.w*c.w;
        #pragma unroll
        for (int o = 16; o > 0; o >>= 1) { s += __shfl_xor_sync(~0u, s, o); ss += __shfl_xor_sync(~0u, ss, o); }
        int warp = threadIdx.x >> 5, lane = threadIdx.x & 31;
        if (lane == 0) { red[warp] = s; red[warp + 8] = ss; }
        __syncthreads();
        s = 0.f; ss = 0.f;
        #pragma unroll
        for (int i = 0; i < 8; i++) { s += red[i]; ss += red[i + 8]; }
        float mu = s * (1.f / DIM);
        float r  = rsqrtf(ss * (1.f / DIM) - mu * mu + LN_EPS);

        float4 w0 = *(const float4*)(w + base), w1 = *(const float4*)(w + base + 4);
        float4 b0 = *(const float4*)(bb + base), b1 = *(const float4*)(bb + base + 4);
        float y[8];
        y[0]=(a.x-mu)*r*w0.x+b0.x; y[1]=(a.y-mu)*r*w0.y+b0.y; y[2]=(a.z-mu)*r*w0.z+b0.z; y[3]=(a.w-mu)*r*w0.w+b0.w;
        y[4]=(c.x-mu)*r*w1.x+b1.x; y[5]=(c.y-mu)*r*w1.y+b1.y; y[6]=(c.z-mu)*r*w1.z+b1.z; y[7]=(c.w-mu)*r*w1.w+b1.w;

        __align__(16) __nv_bfloat16 h[8], l[8];
        #pragma unroll
        for (int i = 0; i < 8; i++) split1(y[i], h[i], l[i]);
        size_t o = (size_t)row * DIM + base;
        *(uint4*)(g_xnh + o) = *(uint4*)h;
        *(uint4*)(g_xnl + o) = *(uint4*)l;
    } else if (id < PREP_WQ0) {
        int i = ((id - PREP_SPL0) * 256 + threadIdx.x) * 4;
        float4 v = *(const float4*)(media + i);
        __align__(8) __nv_bfloat16 h[4], l[4];
        split1(v.x, h[0], l[0]); split1(v.y, h[1], l[1]);
        split1(v.z, h[2], l[2]); split1(v.w, h[3], l[3]);
        *(uint2*)(g_mh + i) = *(uint2*)h;
        *(uint2*)(g_ml + i) = *(uint2*)l;
    } else if (id < PREP_WKV0) {
        int t = id - PREP_WQ0;
        tsplit_body(Wq, g_wqh, g_wql, DIM, INNER, t & 31, t >> 5, tbuf);
    } else if (id < PREP_WO0) {
        int t = id - PREP_WKV0;
        tsplit_body(Wkv, g_wkvh, g_wkvl, DIM_VIS, 2 * INNER, t & 63, t >> 6, tbuf);
    } else if (id < PREP_CUM0) {
        int t = id - PREP_WO0;
        tsplit_body(Wo, g_woh, g_wol, INNER, DIM, t & 63, t >> 6, tbuf);
    } else {
        int b = id - PREP_CUM0;
        int t = threadIdx.x;
        if (t < 32) {
            const unsigned int* row = ml + b * T_TXT;
            int base = t * 64, local = 0;
            int pref[64];
            #pragma unroll 8
            for (int i = 0; i < 64; i++) { local += (row[base + i] != 0u) ? 1 : 0; pref[i] = local; }
            seg[t] = local;
            __syncwarp();
            int off = 0;
            for (int k = 0; k < t; k++) off += seg[k];
            int* out = g_tt + b * T_TXT + base;
            #pragma unroll 8
            for (int i = 0; i < 64; i++) out[i] = off + pref[i];
        }
    }
}

// ============== HMMA split-bf16 GEMM core ==============
// R9 mainloop + nt-PAIR interleaved MMA ordering: accumulator reuse distance
// raised from 2 to 4 MMAs (covers HMMA RAW latency; per-acc accumulation order
// unchanged -> bit-identical results).
#define SST 40                    // smem row stride in bf16 (80 bytes)
#define ARR_B (128 * SST * 2)     // 10240 bytes per array
#define STAGE_B (4 * ARR_B)       // 40960
#define HG_SMEM (2 * STAGE_B)     // 81920

__device__ __forceinline__ void gemm_body(uint32_t sb,
                                          const __nv_bfloat16* Ah_, const __nv_bfloat16* Al_,
                                          const __nv_bfloat16* Bh_, const __nv_bfloat16* Bl_,
                                          float* C, int N, int K, int bm, int bn) {
    int tid = threadIdx.x, lane = tid & 31, wid = tid >> 5;
    int wm = wid >> 1, wn = wid & 1;      // warp grid 4x2

    const __nv_bfloat16* srcs[4] = {
        Ah_ + (size_t)bm * 128 * K, Al_ + (size_t)bm * 128 * K,
        Bh_ + (size_t)bn * 128 * K, Bl_ + (size_t)bn * 128 * K };

    int r0 = lane >> 2;            // 0..7
    int c0 = (lane & 3) * 2;       // 0,2,4,6

    float acc[2][8][4];
    #pragma unroll
    for (int mt = 0; mt < 2; mt++)
        #pragma unroll
        for (int nt = 0; nt < 8; nt++)
            #pragma unroll
            for (int q = 0; q < 4; q++) acc[mt][nt][q] = 0.f;

    int nchunk = K >> 5;

    auto load_chunk = [&](int c, int s) {
        uint32_t sbase = sb + s * STAGE_B;
        #pragma unroll
        for (int arr = 0; arr < 4; arr++) {
            #pragma unroll
            for (int i = 0; i < 2; i++) {
                int o = tid + 256 * i;          // 0..511
                int row = o >> 2, seg = o & 3;
                const void* g = srcs[arr] + (size_t)row * K + c * 32 + seg * 8;
                cp16(sbase + arr * ARR_B + row * (SST * 2) + seg * 16, g);
            }
        }
    };

    load_chunk(0, 0);
    cp_commit();

    for (int c = 0; c < nchunk; c++) {
        if (c + 1 < nchunk) { load_chunk(c + 1, (c + 1) & 1); cp_commit(); cp_wait<1>(); }
        else cp_wait<0>();
        __syncthreads();

        uint32_t st = sb + (c & 1) * STAGE_B;
        uint32_t Ahb = st, Alb = st + ARR_B, Bhb = st + 2 * ARR_B, Blb = st + 3 * ARR_B;

        #pragma unroll
        for (int ks = 0; ks < 2; ks++) {
            int k0 = ks * 16;
            uint32_t ah[2][4], al[2][4];
            #pragma unroll
            for (int mt = 0; mt < 2; mt++) {
                uint32_t ro = (uint32_t)((wm * 32 + mt * 16 + r0) * (SST * 2) + (k0 + c0) * 2);
                ah[mt][0] = lds32(Ahb + ro);
                ah[mt][1] = lds32(Ahb + ro + 8 * (SST * 2));
                ah[mt][2] = lds32(Ahb + ro + 16);
                ah[mt][3] = lds32(Ahb + ro + 8 * (SST * 2) + 16);
                al[mt][0] = lds32(Alb + ro);
                al[mt][1] = lds32(Alb + ro + 8 * (SST * 2));
                al[mt][2] = lds32(Alb + ro + 16);
                al[mt][3] = lds32(Alb + ro + 8 * (SST * 2) + 16);
            }
            // nt-pair interleave: 4 independent accumulators per pass,
            // acc reuse distance = 4 MMAs (was 2).
            #pragma unroll
            for (int np = 0; np < 4; np++) {
                int nt0 = 2 * np, nt1 = nt0 + 1;
                uint32_t no0 = (uint32_t)((wn * 64 + nt0 * 8 + r0) * (SST * 2) + (k0 + c0) * 2);
                uint32_t no1 = (uint32_t)((wn * 64 + nt1 * 8 + r0) * (SST * 2) + (k0 + c0) * 2);
                uint32_t bh0[2], bh1[2], bl0[2], bl1[2];
                bh0[0] = lds32(Bhb + no0); bh0[1] = lds32(Bhb + no0 + 16);
                bh1[0] = lds32(Bhb + no1); bh1[1] = lds32(Bhb + no1 + 16);
                bl0[0] = lds32(Blb + no0); bl0[1] = lds32(Blb + no0 + 16);
                bl1[0] = lds32(Blb + no1); bl1[1] = lds32(Blb + no1 + 16);
                // pass 1: ah x bh
                mma16816(acc[0][nt0], ah[0], bh0);
                mma16816(acc[1][nt0], ah[1], bh0);
                mma16816(acc[0][nt1], ah[0], bh1);
                mma16816(acc[1][nt1], ah[1], bh1);
                // pass 2: ah x bl
                mma16816(acc[0][nt0], ah[0], bl0);
                mma16816(acc[1][nt0], ah[1], bl0);
                mma16816(acc[0][nt1], ah[0], bl1);
                mma16816(acc[1][nt1], ah[1], bl1);
                // pass 3: al x bh
                mma16816(acc[0][nt0], al[0], bh0);
                mma16816(acc[1][nt0], al[1], bh0);
                mma16816(acc[0][nt1], al[0], bh1);
                mma16816(acc[1][nt1], al[1], bh1);
            }
        }
        __syncthreads();
    }

    #pragma unroll
    for (int mt = 0; mt < 2; mt++) {
        int row = bm * 128 + wm * 32 + mt * 16 + r0;
        #pragma unroll
        for (int nt = 0; nt < 8; nt++) {
            int col = bn * 128 + wn * 64 + nt * 8 + c0;
            float* p = C + (size_t)row * N + col;
            *(float2*)p             = make_float2(acc[mt][nt][0], acc[mt][nt][1]);
            *(float2*)(p + 8 * N)   = make_float2(acc[mt][nt][2], acc[mt][nt][3]);
        }
    }
}

// Combined Q+KV GEMM: 512 Q tiles + 256 KV tiles in ONE launch (wave packing).
#define Q_TILES 512    // (8192/128) x (1024/128) = 64 x 8
#define KV_TILES 256   // (2048/128) x (2048/128) = 16 x 16

__global__ __launch_bounds__(256, 2) void hgemm_qkv() {
    extern __shared__ __align__(16) char smem[];
    uint32_t sb = smem_u32(smem);
    int id = blockIdx.x;
    if (id < Q_TILES) {
        int bm = id >> 3, bn = id & 7;
        gemm_body(sb, g_xnh, g_xnl, g_wqh, g_wql, g_q, INNER, DIM, bm, bn);
    } else {
        int t = id - Q_TILES;
        int bm = t >> 4, bn = t & 15;
        gemm_body(sb, g_mh, g_ml, g_wkvh, g_wkvl, g_kv, 2 * INNER, DIM_VIS, bm, bn);
    }
}

// Generic GEMM for the output projection.
__global__ __launch_bounds__(256, 2) void hgemm(const __nv_bfloat16* __restrict__ Ah_,
                                                const __nv_bfloat16* __restrict__ Al_,
                                                const __nv_bfloat16* __restrict__ Bh_,
                                                const __nv_bfloat16* __restrict__ Bl_,
                                                float* __restrict__ C,
                                                int M, int N, int K) {
    extern __shared__ __align__(16) char smem[];
    uint32_t sb = smem_u32(smem);
    gemm_body(sb, Ah_, Al_, Bh_, Bl_, C, N, K, blockIdx.y, blockIdx.x);
}

// ---------------- attention: packed f32x2, K transposed in smem -------------
__device__ __forceinline__ void attn_scalar(const float* __restrict__ qrow,
                                            const float* kb_, const float* vb_,
                                            int ld, __nv_bfloat16* __restrict__ oh,
                                            __nv_bfloat16* __restrict__ ol) {
    float sc[64];
    #pragma unroll
    for (int j = 0; j < 64; j++) sc[j] = 0.f;
    for (int d0 = 0; d0 < 64; d0 += 4) {
        float4 qv = *(const float4*)(qrow + d0);
        #pragma unroll
        for (int j = 0; j < 64; j++) {
            float4 kv = *(const float4*)(kb_ + j * ld + d0);
            sc[j] += qv.x * kv.x + qv.y * kv.y + qv.z * kv.z + qv.w * kv.w;
        }
    }
    float m = sc[0];
    #pragma unroll
    for (int j = 1; j < 64; j++) m = fmaxf(m, sc[j]);
    float sum = 0.f;
    #pragma unroll
    for (int j = 0; j < 64; j++) { float p = __expf((sc[j] - m) * 0.125f); sc[j] = p; sum += p; }
    float inv = 1.f / sum;
    #pragma unroll
    for (int j = 0; j < 64; j++) sc[j] *= inv;
    for (int d0 = 0; d0 < 64; d0 += 4) {
        float o[4] = {0.f, 0.f, 0.f, 0.f};
        #pragma unroll
        for (int j = 0; j < 64; j++) {
            float4 vv = *(const float4*)(vb_ + j * ld + d0);
            o[0] += sc[j] * vv.x; o[1] += sc[j] * vv.y;
            o[2] += sc[j] * vv.z; o[3] += sc[j] * vv.w;
        }
        __align__(8) __nv_bfloat16 h[4], l[4];
        #pragma unroll
        for (int j = 0; j < 4; j++) split1(o[j], h[j], l[j]);
        *(uint2*)(oh + d0) = *(uint2*)h;
        *(uint2*)(ol + d0) = *(uint2*)l;
    }
}

__global__ __launch_bounds__(256) void attn_kernel() {
    __shared__ float KsT[64][68];                 // [d][j], padded
    __shared__ __align__(16) float Vs[64][64];    // [j][d]
    int s = blockIdx.x, h = blockIdx.y, b = blockIdx.z;
    int tid = threadIdx.x;
    int i = s * 256 + tid;

    int tt0 = g_tt[b * T_TXT + s * 256];
    int kb0 = tt0 - 1;
    if (kb0 < 0) kb0 = 0;
    if (kb0 > T_IMG - 1) kb0 = T_IMG - 1;

    const float* kvsrc = g_kv + ((size_t)(b * J_TOT + kb0 * 64)) * (2 * INNER) + h * DIM_HEAD;
    for (int idx = tid; idx < 1024; idx += 256) {
        int j = idx >> 4, d0 = (idx & 15) * 4;
        float4 kk = *(const float4*)(kvsrc + (size_t)j * (2 * INNER) + d0);
        KsT[d0][j] = kk.x; KsT[d0 + 1][j] = kk.y; KsT[d0 + 2][j] = kk.z; KsT[d0 + 3][j] = kk.w;
        *(float4*)(&Vs[j][d0]) = *(const float4*)(kvsrc + (size_t)j * (2 * INNER) + INNER + d0);
    }
    __syncthreads();

    int t = g_tt[b * T_TXT + i];
    size_t obase = (size_t)(b * T_TXT + i) * INNER + h * DIM_HEAD;
    __nv_bfloat16* oh = g_aoh + obase;
    __nv_bfloat16* ol = g_aol + obase;
    if (t == 0) {
        #pragma unroll
        for (int d0 = 0; d0 < 64; d0 += 4) {
            *(uint2*)(oh + d0) = make_uint2(0u, 0u);
            *(uint2*)(ol + d0) = make_uint2(0u, 0u);
        }
        return;
    }
    int kb = t - 1;
    const float* qrow = g_q + (size_t)(b * T_TXT + i) * INNER + h * DIM_HEAD;
    if (kb != kb0) {   // correctness fallback (not taken for the given inputs)
        const float* kg = g_kv + ((size_t)(b * J_TOT + kb * 64)) * (2 * INNER) + h * DIM_HEAD;
        attn_scalar(qrow, kg, kg + INNER, 2 * INNER, oh, ol);
        return;
    }

    // ---- QK^T: packed over j-pairs ----
    unsigned long long sc2[32];
    #pragma unroll
    for (int j = 0; j < 32; j++) sc2[j] = 0ull;
    for (int d0 = 0; d0 < 64; d0 += 4) {
        float4 q4 = *(const float4*)(qrow + d0);
        float qa[4] = {q4.x, q4.y, q4.z, q4.w};
        #pragma unroll
        for (int dd = 0; dd < 4; dd++) {
            unsigned long long qq = pack2(qa[dd], qa[dd]);
            const float* krow = &KsT[d0 + dd][0];
            #pragma unroll
            for (int j4 = 0; j4 < 16; j4++) {
                ulonglong2 kk = *(const ulonglong2*)(krow + j4 * 4);
                ffma2(sc2[2 * j4],     qq, kk.x);
                ffma2(sc2[2 * j4 + 1], qq, kk.y);
            }
        }
    }

    // ---- softmax ----
    float sc[64];
    #pragma unroll
    for (int j = 0; j < 32; j++) unpack2(sc2[j], sc[2 * j], sc[2 * j + 1]);
    float m = sc[0];
    #pragma unroll
    for (int j = 1; j < 64; j++) m = fmaxf(m, sc[j]);
    float sum = 0.f;
    #pragma unroll
    for (int j = 0; j < 64; j++) { float p = __expf((sc[j] - m) * 0.125f); sc[j] = p; sum += p; }
    float inv = 1.f / sum;
    #pragma unroll
    for (int j = 0; j < 64; j++) sc[j] *= inv;

    // ---- P @ V: packed over d-pairs ----
    unsigned long long o2[32];
    #pragma unroll
    for (int d = 0; d < 32; d++) o2[d] = 0ull;
    for (int j = 0; j < 64; j++) {
        unsigned long long pp = pack2(sc[j], sc[j]);
        const float* vrow = &Vs[j][0];
        #pragma unroll
        for (int d4 = 0; d4 < 16; d4++) {
            ulonglong2 vv = *(const ulonglong2*)(vrow + d4 * 4);
            ffma2(o2[2 * d4],     pp, vv.x);
            ffma2(o2[2 * d4 + 1], pp, vv.y);
        }
    }

    #pragma unroll
    for (int d4 = 0; d4 < 16; d4++) {
        float o[4];
        unpack2(o2[2 * d4], o[0], o[1]);
        unpack2(o2[2 * d4 + 1], o[2], o[3]);
        __align__(8) __nv_bfloat16 hh[4], ll[4];
        #pragma unroll
        for (int q = 0; q < 4; q++) split1(o[q], hh[q], ll[q]);
        *(uint2*)(oh + d4 * 4) = *(uint2*)hh;
        *(uint2*)(ol + d4 * 4) = *(uint2*)ll;
    }
}

// ---------------- launch ----------------
extern "C" void kernel_launch(void* const* d_in, const int* in_sizes, int n_in,
                              void* d_out, int out_size) {
    const float* x     = (const float*)d_in[0];
    const float* media = (const float*)d_in[1];
    const float* nw    = (const float*)d_in[2];
    const float* nb    = (const float*)d_in[3];
    const float* Wq    = (const float*)d_in[4];
    const float* Wkv   = (const float*)d_in[5];
    const float* Wo    = (const float*)d_in[6];
    const unsigned int* ml = (const unsigned int*)d_in[7];
    float* out = (float*)d_out;

    cudaFuncSetAttribute(hgemm, cudaFuncAttributeMaxDynamicSharedMemorySize, HG_SMEM);
    cudaFuncSetAttribute(hgemm_qkv, cudaFuncAttributeMaxDynamicSharedMemorySize, HG_SMEM);

    void *p_aoh, *p_aol, *p_woh, *p_wol;
    cudaGetSymbolAddress(&p_aoh, g_aoh);  cudaGetSymbolAddress(&p_aol, g_aol);
    cudaGetSymbolAddress(&p_woh, g_woh);  cudaGetSymbolAddress(&p_wol, g_wol);

    // All pre-processing in ONE launch (ln + media split + 3 tsplits + cumsum)
    prep_kernel<<<PREP_BLOCKS, 256>>>(x, nw, nb, media, Wq, Wkv, Wo, ml);

    // Q + KV in one launch (768 CTAs, wave packing at 2 CTAs/SM)
    hgemm_qkv<<<Q_TILES + KV_TILES, 256, HG_SMEM>>>();

    attn_kernel<<<dim3(T_TXT / 256, HEADS, BB), 256>>>();

    // out = ao @ Wo : M=8192, N=2048, K=1024
    hgemm<<<dim3(DIM / 128, MTOT / 128), 256, HG_SMEM>>>(
        (const __nv_bfloat16*)p_aoh, (const __nv_bfloat16*)p_aol,
        (const __nv_bfloat16*)p_woh, (const __nv_bfloat16*)p_wol,
        out, MTOT, DIM, INNER);
}